// round 14
// baseline (speedup 1.0000x reference)
#include <cuda_runtime.h>
#include <cuda_bf16.h>
#include <math.h>
#include <stdint.h>

#define BB 2
#define HH 128
#define WW 256
#define CCH 768
#define KWV 65
#define NB 8
#define BS 96
#define NPOS (BB*HH*KWV)
#define SLABN (NPOS*CCH)

typedef unsigned long long u64;
typedef __nv_bfloat162 cbf;

__device__ cbf g_A[SLABN];                 // 51 MB: complex slab / interleaved (S,D) slab
__device__ cbf g_B[SLABN];                 // 51 MB
__device__ __nv_bfloat16 g_C[SLABN];       // 25.5 MB: an gather slab (real bf16)
__device__ float2 g_tw256[256];
__device__ float2 g_tw768[768];
__device__ float2 g_tw128[128];

#define WSTR 104
__device__ __nv_bfloat16 g_Wb[4][NB][BS*WSTR];   // pre-transposed bf16 weights [o][i]

__device__ __forceinline__ float2 b2f(cbf v) {
    return make_float2(__bfloat162float(v.x), __bfloat162float(v.y));
}
__device__ __forceinline__ cbf f2b(float2 v) {
    return __floats2bfloat162_rn(v.x, v.y);
}
__device__ __forceinline__ void cmadd(float2& acc, float2 z, float2 t) {
    acc.x = fmaf(z.x, t.x, fmaf(-z.y, t.y, acc.x));
    acc.y = fmaf(z.x, t.y, fmaf( z.y, t.x, acc.y));
}
__device__ __forceinline__ float2 cmul(float2 a, float2 b) {
    return make_float2(a.x*b.x - a.y*b.y, a.x*b.y + a.y*b.x);
}

// ---------------- register FFT primitives ----------------
#define FC1 0.92387953251128674f
#define FS1 0.38268343236508977f
#define FR  0.70710678118654752f

__device__ __forceinline__ float2 cadd2(float2 a, float2 b) {
    return make_float2(fmaf(b.x, 1.0f, a.x), fmaf(b.y, 1.0f, a.y));
}
__device__ __forceinline__ float2 csub2(float2 a, float2 b) {
    return make_float2(fmaf(b.x, -1.0f, a.x), fmaf(b.y, -1.0f, a.y));
}
__device__ __forceinline__ float2 cmulK(float2 z, float C, float S) {
    return make_float2(fmaf(z.x, C, -z.y*S), fmaf(z.y, C, z.x*S));
}
__device__ __forceinline__ void dft4(float2& a, float2& b, float2& c, float2& d) {
    float2 apc = cadd2(a, c), amc = csub2(a, c);
    float2 bpd = cadd2(b, d), bmd = csub2(b, d);
    float2 jb = make_float2(bmd.y, -bmd.x);
    a = cadd2(apc, bpd);
    b = cadd2(amc, jb);
    c = csub2(apc, bpd);
    d = csub2(amc, jb);
}
#define FFI(k) (4*((k)&3) + ((k)>>2))
__device__ __forceinline__ void fft16r(float2 v[16]) {
    dft4(v[0], v[4], v[8],  v[12]);
    dft4(v[1], v[5], v[9],  v[13]);
    dft4(v[2], v[6], v[10], v[14]);
    dft4(v[3], v[7], v[11], v[15]);
    v[5]  = cmulK(v[5],  FC1, -FS1);
    v[6]  = cmulK(v[6],  FR,  -FR );
    v[7]  = cmulK(v[7],  FS1, -FC1);
    v[9]  = cmulK(v[9],  FR,  -FR );
    v[10] = make_float2(v[10].y, -v[10].x);
    v[11] = cmulK(v[11], -FR,  -FR );
    v[13] = cmulK(v[13], FS1, -FC1);
    v[14] = cmulK(v[14], -FR,  -FR );
    v[15] = cmulK(v[15], -FC1,  FS1);
    dft4(v[0],  v[1],  v[2],  v[3]);
    dft4(v[4],  v[5],  v[6],  v[7]);
    dft4(v[8],  v[9],  v[10], v[11]);
    dft4(v[12], v[13], v[14], v[15]);
}
__device__ __forceinline__ void fft8r(float2 v[8]) {
    float2 a0 = cadd2(v[0], v[4]), a1 = cadd2(v[1], v[5]);
    float2 a2 = cadd2(v[2], v[6]), a3 = cadd2(v[3], v[7]);
    float2 b0 = csub2(v[0], v[4]);
    float2 t1 = csub2(v[1], v[5]);
    float2 t2 = csub2(v[2], v[6]);
    float2 t3 = csub2(v[3], v[7]);
    float2 b1 = cmulK(t1, FR, -FR);
    float2 b2 = make_float2(t2.y, -t2.x);
    float2 b3 = cmulK(t3, -FR, -FR);
    dft4(a0, a1, a2, a3);
    dft4(b0, b1, b2, b3);
    v[0] = a0; v[2] = a1; v[4] = a2; v[6] = a3;
    v[1] = b0; v[3] = b1; v[5] = b2; v[7] = b3;
}

// ---------------- HMMA helpers ----------------
__device__ __forceinline__ uint32_t smem_u32(const void* p) {
    uint32_t a;
    asm("{ .reg .u64 t; cvta.to.shared.u64 t, %1; cvt.u32.u64 %0, t; }" : "=r"(a) : "l"(p));
    return a;
}
__device__ __forceinline__ void ldmA(unsigned r[4], uint32_t addr) {
    asm volatile("ldmatrix.sync.aligned.m8n8.x4.shared.b16 {%0,%1,%2,%3}, [%4];"
        : "=r"(r[0]),"=r"(r[1]),"=r"(r[2]),"=r"(r[3]) : "r"(addr));
}
__device__ __forceinline__ void mma16816(float d[4], const unsigned a[4], const unsigned b[2]) {
    asm volatile("mma.sync.aligned.m16n8k16.row.col.f32.bf16.bf16.f32 "
        "{%0,%1,%2,%3}, {%4,%5,%6,%7}, {%8,%9}, {%0,%1,%2,%3};"
        : "+f"(d[0]),"+f"(d[1]),"+f"(d[2]),"+f"(d[3])
        : "r"(a[0]),"r"(a[1]),"r"(a[2]),"r"(a[3]), "r"(b[0]),"r"(b[1]));
}

// ---------------- prep: twiddles + bf16 weight transposition ----------------
__global__ void kPrep(const float* __restrict__ w1, const float* __restrict__ w2)
{
    int t = blockIdx.x * blockDim.x + threadIdx.x;
    const double TP = 6.283185307179586476925286766559;
    if (t < 768) {
        double s, c;
        sincos(-TP * (double)t / 768.0, &s, &c);
        g_tw768[t] = make_float2((float)c, (float)s);
        if (t < 256) { sincos(-TP*(double)t/256.0, &s, &c); g_tw256[t] = make_float2((float)c,(float)s); }
        if (t < 128) { sincos(-TP*(double)t/128.0, &s, &c); g_tw128[t] = make_float2((float)c,(float)s); }
    }
    int stride = gridDim.x * blockDim.x;
    for (int e = t; e < 4*NB*BS*BS; e += stride) {
        int m = e / (NB*BS*BS);
        int r = e - m*(NB*BS*BS);
        int n = r / (BS*BS);
        int q = r - n*(BS*BS);
        int i = q / BS, o = q - i*BS;
        const float* src = (m < 2) ? (w1 + (size_t)(m*NB + n)*9216)
                                   : (w2 + (size_t)((m-2)*NB + n)*9216);
        g_Wb[m][n][o*WSTR + i] = __float2bfloat16(src[i*96 + o]);
    }
}

// ---------------- forward W-FFT (256=16x16) pruned kw<65 + an emit : x -> g_A, g_C ----------------
__global__ __launch_bounds__(256) void kF1(const float* __restrict__ x)
{
    extern __shared__ float smF1[];
    float*  Xs  = smF1;
    float2* Ys  = (float2*)(smF1 + 4352);
    float2* stw = Ys + 4352;
    const int bh = blockIdx.x, c0 = blockIdx.y * 16, tid = threadIdx.x;
    if (tid < 256) stw[tid] = g_tw256[tid];
    const float* xp = x + (size_t)bh * (WW*CCH) + c0;
    for (int e = tid; e < 4096; e += 256)
        Xs[(e >> 4)*17 + (e & 15)] = xp[(size_t)(e >> 4) * CCH + (e & 15)];
    __syncthreads();
    {
        const int b = bh >> 7, h = bh & 127;
        const int hn = (HH - h) & (HH - 1);
        __nv_bfloat16* cp = g_C + (((size_t)b*HH + hn)*KWV)*CCH + c0;
        for (int e = tid; e < KWV*16; e += 256) {
            int kw = e >> 4, c = e & 15;
            int wn = (WW - kw) & (WW - 1);
            cp[(size_t)kw*CCH + c] = __float2bfloat16(Xs[wn*17 + c]);
        }
    }
    {
        const int n2 = tid >> 4, c = tid & 15;
        float2 u[16];
        #pragma unroll
        for (int n1 = 0; n1 < 16; n1++) u[n1] = make_float2(Xs[(16*n1 + n2)*17 + c], 0.f);
        fft16r(u);
        #pragma unroll
        for (int k1 = 0; k1 < 16; k1++)
            Ys[(k1*16 + n2)*17 + c] = cmul(u[FFI(k1)], stw[n2*k1]);
    }
    __syncthreads();
    {
        const int k1 = tid >> 4, c = tid & 15;
        float2 v[16];
        #pragma unroll
        for (int n2 = 0; n2 < 16; n2++) v[n2] = Ys[(k1*16 + n2)*17 + c];
        fft16r(v);
        cbf* dst = g_A + ((size_t)bh*KWV)*CCH + c0 + c;
        #pragma unroll
        for (int k2 = 0; k2 < 4; k2++)
            dst[(size_t)(k1 + 16*k2)*CCH] = f2b(v[FFI(k2)]);
        if (k1 == 0)
            dst[(size_t)64*CCH] = f2b(v[FFI(4)]);
    }
}

// ---------------- C-FFT 768 = 16x16x3 : RIN=0: g_A->g_B; RIN=1: real(bf16) g_B->g_A ----------------
template<int RIN>
__global__ __launch_bounds__(192) void kFC()
{
    extern __shared__ char smCb[];
    cbf*    zb     = (cbf*)smCb;
    float2* Ab     = (float2*)(smCb + 12288);
    float2* stw256 = (float2*)(smCb + 36864);
    float2* stw768 = (float2*)(smCb + 38912);
    const int tid = threadIdx.x;
    const int r = tid / 48, l = tid - r*48;
    const size_t row0 = (size_t)blockIdx.x * 4;
    for (int e = tid; e < 256; e += 192) stw256[e] = g_tw256[e];
    for (int e = tid; e < 512; e += 192) stw768[e] = g_tw768[e];
    if (RIN) {
        const __nv_bfloat16* sp = (const __nv_bfloat16*)g_B;
        for (int e = tid; e < 3072; e += 192) {
            cbf z; z.x = sp[row0*768 + e]; z.y = __float2bfloat16(0.f);
            zb[e] = z;
        }
    } else {
        const uint4* sp = (const uint4*)(g_A + row0*768);
        uint4* dp = (uint4*)zb;
        for (int e = tid; e < 768; e += 192)
            dp[e] = sp[e];
    }
    __syncthreads();
    {
        const int n3 = l >> 4, n2 = l & 15;
        float2 u[16];
        #pragma unroll
        for (int n1 = 0; n1 < 16; n1++) u[n1] = b2f(zb[r*768 + n3 + 3*n2 + 48*n1]);
        fft16r(u);
        #pragma unroll
        for (int k1 = 0; k1 < 16; k1++)
            Ab[r*768 + (n3*16 + k1)*16 + n2] = cmul(u[FFI(k1)], stw256[n2*k1]);
    }
    __syncthreads();
    {
        const int n3 = l >> 4, k1 = l & 15;
        float2 v[16];
        #pragma unroll
        for (int n2 = 0; n2 < 16; n2++) v[n2] = Ab[r*768 + (n3*16 + k1)*16 + n2];
        fft16r(v);
        #pragma unroll
        for (int k2 = 0; k2 < 16; k2++)
            zb[r*768 + (n3*16 + k1)*16 + k2] = f2b(v[FFI(k2)]);
    }
    __syncthreads();
    {
        cbf* dst = RIN ? g_A : g_B;
        const float s3 = 0.86602540378443865f;
        for (int e = tid; e < 1024; e += 192) {
            const int rr = e >> 8, m = e & 255;
            const int k1 = m & 15, k2 = m >> 4;
            float2 b0 = b2f(zb[rr*768 +       k1*16 + k2]);
            float2 b1 = cmul(b2f(zb[rr*768 + 256 + k1*16 + k2]), stw768[m]);
            float2 b2 = cmul(b2f(zb[rr*768 + 512 + k1*16 + k2]), stw768[2*m]);
            float2 t1 = make_float2(b1.x + b2.x, b1.y + b2.y);
            float2 t2 = make_float2(b1.x - b2.x, b1.y - b2.y);
            dst[(row0+rr)*768 + m] = f2b(make_float2(b0.x + t1.x, b0.y + t1.y));
            float xr = fmaf(-0.5f, t1.x, b0.x);
            float xi = fmaf(-0.5f, t1.y, b0.y);
            dst[(row0+rr)*768 + m + 256] = f2b(make_float2(fmaf( s3, t2.y, xr), fmaf(-s3, t2.x, xi)));
            dst[(row0+rr)*768 + m + 512] = f2b(make_float2(fmaf(-s3, t2.y, xr), fmaf( s3, t2.x, xi)));
        }
    }
}

// ---------------- H-FFT (128=16x8) + B-FFT.  FWD=1: g_B(+g_C an) -> interleaved S/D in g_A ; FWD=0: g_A -> g_B ----------------
template<int FWD>
__global__ __launch_bounds__(256) void kFHB()
{
    __shared__ float2 Ys[2][16][8][16];
    __shared__ float2 stw[128];
    const cbf* __restrict__ src = FWD ? g_B : g_A;
    const int kw = blockIdx.x, c0 = blockIdx.y * 16, tid = threadIdx.x;
    if (tid < 128) stw[tid] = g_tw128[tid];
    {
        const int c = tid & 15, n2 = (tid >> 4) & 7, bb = tid >> 7;
        const size_t hstep = (size_t)8 * KWV * CCH;
        const cbf* p0 = src + ((size_t)n2 * KWV + kw)*CCH + c0 + c;
        const cbf* p1 = p0 + (size_t)HH * KWV * CCH;
        float2 u[16];
        #pragma unroll
        for (int n1 = 0; n1 < 16; n1++) {
            float2 a = b2f(*p0), b = b2f(*p1);
            p0 += hstep; p1 += hstep;
            u[n1] = bb ? make_float2(a.x - b.x, a.y - b.y)
                       : make_float2(a.x + b.x, a.y + b.y);
        }
        __syncthreads();
        fft16r(u);
        #pragma unroll
        for (int k1 = 0; k1 < 16; k1++)
            Ys[bb][k1][n2][c] = cmul(u[FFI(k1)], stw[k1*n2]);
    }
    __syncthreads();
    #pragma unroll
    for (int r = 0; r < 2; r++) {
        int t = tid + 256*r;
        int c = t & 15, k1 = (t >> 4) & 15, bb = t >> 8;
        float2 v[8];
        #pragma unroll
        for (int n2 = 0; n2 < 8; n2++) v[n2] = Ys[bb][k1][n2][c];
        fft8r(v);
        const size_t kstep = (size_t)16 * KWV * CCH;
        const size_t base = (((size_t)bb*HH + k1)*KWV + kw)*CCH + c0 + c;
        if (FWD) {
            // interleaved emit: g_A[idx] = (S, D) as one 4-byte cbf
            cbf* q = g_A + base;
            const __nv_bfloat16* qa = g_C + base;
            #pragma unroll
            for (int k2 = 0; k2 < 8; k2++) {
                float av = v[k2].x + v[k2].y;
                float an = __bfloat162float(*qa);
                *q = __floats2bfloat162_rn(av + an, av - an);
                q += kstep; qa += kstep;
            }
        } else {
            cbf* q = g_B + base;
            #pragma unroll
            for (int k2 = 0; k2 < 8; k2++) {
                *q = f2b(v[k2]);
                q += kstep;
            }
        }
    }
}

// ---------------- HMMA MLP: g_A (interleaved S/D) -> s (bf16) in g_B ----------------
#define MO_AS 0
#define MO_AD 26624
#define MO_W0 53248
#define MO_W1 73216
#define MSM   93184
#define ASTR  104
#define SOP   133

__device__ __forceinline__ void mmaGemv(uint32_t aSb, uint32_t aDb,
    const __nv_bfloat16* __restrict__ w0, const __nv_bfloat16* __restrict__ w1v,
    int warpM, int warpN, int lane, int g, int tig,
    float U[2][3][4], float V[2][3][4])
{
    #pragma unroll
    for (int mi = 0; mi < 2; mi++)
        #pragma unroll
        for (int ni = 0; ni < 3; ni++)
            #pragma unroll
            for (int j = 0; j < 4; j++) { U[mi][ni][j] = 0.f; V[mi][ni][j] = 0.f; }
    const uint32_t lrow = (uint32_t)(lane & 15) * (ASTR*2);
    const uint32_t lcol = (uint32_t)((lane >> 4) << 4);
    #pragma unroll
    for (int kb = 0; kb < 6; kb++) {
        const int kc = kb * 16;
        unsigned aS0[4], aS1[4], aD0[4], aD1[4];
        uint32_t base = lrow + lcol + kc*2;
        ldmA(aS0, aSb + (uint32_t)(warpM*32     )*(ASTR*2) + base);
        ldmA(aS1, aSb + (uint32_t)(warpM*32 + 16)*(ASTR*2) + base);
        ldmA(aD0, aDb + (uint32_t)(warpM*32     )*(ASTR*2) + base);
        ldmA(aD1, aDb + (uint32_t)(warpM*32 + 16)*(ASTR*2) + base);
        #pragma unroll
        for (int ni = 0; ni < 3; ni++) {
            const int orow = warpN*24 + ni*8 + g;
            unsigned b0[2], b1[2];
            b0[0] = *(const unsigned*)&w0 [orow*WSTR + kc + 2*tig];
            b0[1] = *(const unsigned*)&w0 [orow*WSTR + kc + 8 + 2*tig];
            b1[0] = *(const unsigned*)&w1v[orow*WSTR + kc + 2*tig];
            b1[1] = *(const unsigned*)&w1v[orow*WSTR + kc + 8 + 2*tig];
            mma16816(U[0][ni], aS0, b0);
            mma16816(U[1][ni], aS1, b0);
            mma16816(V[0][ni], aD0, b1);
            mma16816(V[1][ni], aD1, b1);
        }
    }
}

__global__ __launch_bounds__(512, 1) void kMLP(const float* __restrict__ b1,
                                               const float* __restrict__ b2)
{
    extern __shared__ char smc[];
    __nv_bfloat16* aS  = (__nv_bfloat16*)(smc + MO_AS);
    __nv_bfloat16* aD  = (__nv_bfloat16*)(smc + MO_AD);
    __nv_bfloat16* wS0 = (__nv_bfloat16*)(smc + MO_W0);
    __nv_bfloat16* wS1 = (__nv_bfloat16*)(smc + MO_W1);
    const uint32_t aSb = smem_u32(aS), aDb = smem_u32(aD);
    const int n = blockIdx.y, p0 = blockIdx.x * 128, tid = threadIdx.x;
    const int wid = tid >> 5, lane = tid & 31;
    const int warpM = wid >> 2, warpN = wid & 3;
    const int g = lane >> 2, tig = lane & 3;

    {
        const uint4* s0 = (const uint4*)g_Wb[0][n];
        const uint4* s1 = (const uint4*)g_Wb[1][n];
        for (int e = tid; e < (BS*WSTR)/8; e += 512) {
            ((uint4*)wS0)[e] = s0[e];
            ((uint4*)wS1)[e] = s1[e];
        }
    }
    // activation staging: coalesced cbf loads, split into aS/aD
    {
        const cbf* gSD = g_A + (size_t)p0*CCH + n*BS;
        for (int e = tid; e < 12288; e += 512) {
            int p = e / 96, c = e - 96*p;
            cbf z = gSD[(size_t)p*CCH + c];
            aS[p*ASTR + c] = z.x;
            aD[p*ASTR + c] = z.y;
        }
    }
    __syncthreads();

    float U[2][3][4], V[2][3][4], keep[2][3][4];

    // ===== layer 1 =====
    mmaGemv(aSb, aDb, wS0, wS1, warpM, warpN, lane, g, tig, U, V);
    __syncthreads();
    #pragma unroll
    for (int mi = 0; mi < 2; mi++)
        #pragma unroll
        for (int ni = 0; ni < 3; ni++) {
            const int o = warpN*24 + ni*8 + 2*tig;
            const float bk0 = b1[n*BS + o],        bk1 = b1[n*BS + o + 1];
            const float bn0 = b1[(NB+n)*BS + o],   bn1 = b1[(NB+n)*BS + o + 1];
            const int p = warpM*32 + mi*16 + g;
            #pragma unroll
            for (int hh = 0; hh < 2; hh++) {
                float Uu0 = U[mi][ni][2*hh], Uu1 = U[mi][ni][2*hh+1];
                float Vv0 = V[mi][ni][2*hh], Vv1 = V[mi][ni][2*hh+1];
                float k0 = fmaxf(fmaf(0.5f, Uu0 + Vv0, bk0), 0.f);
                float n0 = fmaxf(fmaf(0.5f, Uu0 - Vv0, bn0), 0.f);
                float k1 = fmaxf(fmaf(0.5f, Uu1 + Vv1, bk1), 0.f);
                float n1 = fmaxf(fmaf(0.5f, Uu1 - Vv1, bn1), 0.f);
                keep[mi][ni][2*hh] = n0; keep[mi][ni][2*hh+1] = n1;
                const int pp = p + 8*hh;
                *(__nv_bfloat162*)&aS[pp*ASTR + o] = __floats2bfloat162_rn(k0 + n0, k1 + n1);
                *(__nv_bfloat162*)&aD[pp*ASTR + o] = __floats2bfloat162_rn(k0 - n0, k1 - n1);
            }
        }
    {
        const uint4* s0 = (const uint4*)g_Wb[2][n];
        const uint4* s1 = (const uint4*)g_Wb[3][n];
        for (int e = tid; e < (BS*WSTR)/8; e += 512) {
            ((uint4*)wS0)[e] = s0[e];
            ((uint4*)wS1)[e] = s1[e];
        }
    }
    __syncthreads();

    // ===== layer 2 (o2_k) =====
    mmaGemv(aSb, aDb, wS0, wS1, warpM, warpN, lane, g, tig, U, V);
    __syncthreads();
    #pragma unroll
    for (int mi = 0; mi < 2; mi++)
        #pragma unroll
        for (int ni = 0; ni < 3; ni++) {
            const int o = warpN*24 + ni*8 + 2*tig;
            const float bk0 = b2[n*BS + o], bk1 = b2[n*BS + o + 1];
            const int p = warpM*32 + mi*16 + g;
            #pragma unroll
            for (int hh = 0; hh < 2; hh++) {
                float ok0 = fmaf(0.5f, U[mi][ni][2*hh]   + V[mi][ni][2*hh],   bk0);
                float ok1 = fmaf(0.5f, U[mi][ni][2*hh+1] + V[mi][ni][2*hh+1], bk1);
                float un0 = keep[mi][ni][2*hh], un1 = keep[mi][ni][2*hh+1];
                keep[mi][ni][2*hh] = ok0; keep[mi][ni][2*hh+1] = ok1;
                const int pp = p + 8*hh;
                *(__nv_bfloat162*)&aS[pp*ASTR + o] = __floats2bfloat162_rn(un0 + ok0, un1 + ok1);
                *(__nv_bfloat162*)&aD[pp*ASTR + o] = __floats2bfloat162_rn(un0 - ok0, un1 - ok1);  // o2_nk uses o2_k
            }
        }
    __syncthreads();

    // ===== layer 2 (o2_nk) + soft-threshold =====
    mmaGemv(aSb, aDb, wS0, wS1, warpM, warpN, lane, g, tig, U, V);
    __syncthreads();
    float* sOut = (float*)(smc + MO_AS);
    #pragma unroll
    for (int mi = 0; mi < 2; mi++)
        #pragma unroll
        for (int ni = 0; ni < 3; ni++) {
            const int o = warpN*24 + ni*8 + 2*tig;
            const float bn0 = b2[(NB+n)*BS + o], bn1 = b2[(NB+n)*BS + o + 1];
            const int p = warpM*32 + mi*16 + g;
            #pragma unroll
            for (int hh = 0; hh < 2; hh++) {
                float o2n0 = fmaf(0.5f, U[mi][ni][2*hh]   + V[mi][ni][2*hh],   bn0);
                float o2n1 = fmaf(0.5f, U[mi][ni][2*hh+1] + V[mi][ni][2*hh+1], bn1);
                float t0 = keep[mi][ni][2*hh]   + o2n0;
                float t1 = keep[mi][ni][2*hh+1] + o2n1;
                const int pp = p + 8*hh;
                sOut[o*SOP + pp]     = copysignf(fmaxf(fabsf(t0) - 0.01f, 0.f), t0);
                sOut[(o+1)*SOP + pp] = copysignf(fmaxf(fabsf(t1) - 0.01f, 0.f), t1);
            }
        }
    __syncthreads();
    __nv_bfloat16* outp = (__nv_bfloat16*)g_B;
    for (int e = tid; e < 12288; e += 512) {
        int p = e / 96, c = e - 96*p;
        outp[(size_t)(p0 + p)*CCH + n*BS + c] = __float2bfloat16(sOut[c*SOP + p]);
    }
}

// ---------------- inverse W-FFT (65 -> 256) + scale + residual : g_B -> out ----------------
__global__ __launch_bounds__(256) void kIW(const float* __restrict__ x, float* __restrict__ out)
{
    __shared__ float2 Zs[KWV*16];
    __shared__ float2 Ys[256*17];
    __shared__ float2 stw[256];
    const int bh = blockIdx.x, c0 = blockIdx.y * 16, tid = threadIdx.x;
    if (tid < 256) stw[tid] = g_tw256[tid];
    const cbf* __restrict__ zp = g_B + (size_t)bh*KWV*CCH + c0;
    for (int e = tid; e < KWV*16; e += 256) {
        int w = e >> 4, c = e & 15;
        Zs[e] = b2f(zp[(size_t)w*CCH + c]);
    }
    __syncthreads();
    for (int e = tid; e < 4096; e += 256) {
        int c = e & 15, n2 = (e >> 4) & 15, k1 = e >> 8;
        float2 acc = make_float2(0.f, 0.f);
        int idx = (k1 * n2) & 255, step = (k1 * 16) & 255;
        int nmax = (n2 == 0) ? 5 : 4;
        for (int n1 = 0; n1 < nmax; n1++) {
            int w = (n1 << 4) + n2;
            cmadd(acc, Zs[w*16 + c], stw[idx]);
            idx = (idx + step) & 255;
        }
        Ys[(k1*16 + n2)*17 + c] = acc;
    }
    __syncthreads();
    const float invN = 1.0f / 50331648.0f;
    {
        const int k1 = tid >> 4, c = tid & 15;
        float2 v[16];
        #pragma unroll
        for (int n2 = 0; n2 < 16; n2++) v[n2] = Ys[(k1*16 + n2)*17 + c];
        fft16r(v);
        #pragma unroll
        for (int k2 = 0; k2 < 16; k2++) {
            float2 acc = v[FFI(k2)];
            size_t a = ((size_t)bh*WW + k1 + 16*k2)*CCH + c0 + c;
            out[a] = fmaf(acc.x + acc.y, invN, x[a]);
        }
    }
}

extern "C" void kernel_launch(void* const* d_in, const int* in_sizes, int n_in,
                              void* d_out, int out_size)
{
    const float* x  = (const float*)d_in[0];
    const float* w1 = (const float*)d_in[1];
    const float* b1 = (const float*)d_in[2];
    const float* w2 = (const float*)d_in[3];
    const float* b2 = (const float*)d_in[4];
    float* out = (float*)d_out;

    cudaFuncSetAttribute(kMLP,   cudaFuncAttributeMaxDynamicSharedMemorySize, MSM);
    cudaFuncSetAttribute(kF1,    cudaFuncAttributeMaxDynamicSharedMemorySize, 54272);
    cudaFuncSetAttribute(kFC<0>, cudaFuncAttributeMaxDynamicSharedMemorySize, 43008);
    cudaFuncSetAttribute(kFC<1>, cudaFuncAttributeMaxDynamicSharedMemorySize, 43008);

    kPrep<<<290, 1024>>>(w1, w2);
    kF1 <<<dim3(BB*HH, CCH/16), 256, 54272>>>(x);   // x -> A (cplx) + C (an)
    kFC<0><<<NPOS/4, 192, 43008>>>();               // A -> B
    kFHB<1><<<dim3(KWV, CCH/16), 256>>>();          // B (+C) -> interleaved S/D in A
    kMLP<<<dim3(NPOS/128, NB), 512, MSM>>>(b1, b2); // A(S/D) -> s(bf16) in B
    kFC<1><<<NPOS/4, 192, 43008>>>();               // B(real bf16) -> A
    kFHB<0><<<dim3(KWV, CCH/16), 256>>>();          // A -> B
    kIW <<<dim3(BB*HH, CCH/16), 256>>>(x, out);     // B -> out
}

// round 15
// speedup vs baseline: 1.0213x; 1.0213x over previous
#include <cuda_runtime.h>
#include <cuda_bf16.h>
#include <math.h>
#include <stdint.h>

#define BB 2
#define HH 128
#define WW 256
#define CCH 768
#define KWV 65
#define NB 8
#define BS 96
#define NPOS (BB*HH*KWV)
#define SLABN (NPOS*CCH)

typedef unsigned long long u64;
typedef __nv_bfloat162 cbf;

__device__ cbf g_A[SLABN];                 // 51 MB: complex slab / av real slab (bf16)
__device__ cbf g_B[SLABN];                 // 51 MB
__device__ __nv_bfloat16 g_C[SLABN];       // 25.5 MB: an gather slab (real bf16)
__device__ float2 g_tw256[256];
__device__ float2 g_tw768[768];
__device__ float2 g_tw128[128];

#define WSTR 104
__device__ __nv_bfloat16 g_Wb[4][NB][BS*WSTR];   // pre-transposed bf16 weights [o][i]

__device__ __forceinline__ float2 b2f(cbf v) {
    return make_float2(__bfloat162float(v.x), __bfloat162float(v.y));
}
__device__ __forceinline__ cbf f2b(float2 v) {
    return __floats2bfloat162_rn(v.x, v.y);
}
__device__ __forceinline__ void cmadd(float2& acc, float2 z, float2 t) {
    acc.x = fmaf(z.x, t.x, fmaf(-z.y, t.y, acc.x));
    acc.y = fmaf(z.x, t.y, fmaf( z.y, t.x, acc.y));
}
__device__ __forceinline__ float2 cmul(float2 a, float2 b) {
    return make_float2(a.x*b.x - a.y*b.y, a.x*b.y + a.y*b.x);
}

// ---------------- register FFT primitives ----------------
#define FC1 0.92387953251128674f
#define FS1 0.38268343236508977f
#define FR  0.70710678118654752f

__device__ __forceinline__ float2 cadd2(float2 a, float2 b) {
    return make_float2(fmaf(b.x, 1.0f, a.x), fmaf(b.y, 1.0f, a.y));
}
__device__ __forceinline__ float2 csub2(float2 a, float2 b) {
    return make_float2(fmaf(b.x, -1.0f, a.x), fmaf(b.y, -1.0f, a.y));
}
__device__ __forceinline__ float2 cmulK(float2 z, float C, float S) {
    return make_float2(fmaf(z.x, C, -z.y*S), fmaf(z.y, C, z.x*S));
}
__device__ __forceinline__ void dft4(float2& a, float2& b, float2& c, float2& d) {
    float2 apc = cadd2(a, c), amc = csub2(a, c);
    float2 bpd = cadd2(b, d), bmd = csub2(b, d);
    float2 jb = make_float2(bmd.y, -bmd.x);
    a = cadd2(apc, bpd);
    b = cadd2(amc, jb);
    c = csub2(apc, bpd);
    d = csub2(amc, jb);
}
#define FFI(k) (4*((k)&3) + ((k)>>2))
__device__ __forceinline__ void fft16r(float2 v[16]) {
    dft4(v[0], v[4], v[8],  v[12]);
    dft4(v[1], v[5], v[9],  v[13]);
    dft4(v[2], v[6], v[10], v[14]);
    dft4(v[3], v[7], v[11], v[15]);
    v[5]  = cmulK(v[5],  FC1, -FS1);
    v[6]  = cmulK(v[6],  FR,  -FR );
    v[7]  = cmulK(v[7],  FS1, -FC1);
    v[9]  = cmulK(v[9],  FR,  -FR );
    v[10] = make_float2(v[10].y, -v[10].x);
    v[11] = cmulK(v[11], -FR,  -FR );
    v[13] = cmulK(v[13], FS1, -FC1);
    v[14] = cmulK(v[14], -FR,  -FR );
    v[15] = cmulK(v[15], -FC1,  FS1);
    dft4(v[0],  v[1],  v[2],  v[3]);
    dft4(v[4],  v[5],  v[6],  v[7]);
    dft4(v[8],  v[9],  v[10], v[11]);
    dft4(v[12], v[13], v[14], v[15]);
}
__device__ __forceinline__ void fft8r(float2 v[8]) {
    float2 a0 = cadd2(v[0], v[4]), a1 = cadd2(v[1], v[5]);
    float2 a2 = cadd2(v[2], v[6]), a3 = cadd2(v[3], v[7]);
    float2 b0 = csub2(v[0], v[4]);
    float2 t1 = csub2(v[1], v[5]);
    float2 t2 = csub2(v[2], v[6]);
    float2 t3 = csub2(v[3], v[7]);
    float2 b1 = cmulK(t1, FR, -FR);
    float2 b2 = make_float2(t2.y, -t2.x);
    float2 b3 = cmulK(t3, -FR, -FR);
    dft4(a0, a1, a2, a3);
    dft4(b0, b1, b2, b3);
    v[0] = a0; v[2] = a1; v[4] = a2; v[6] = a3;
    v[1] = b0; v[3] = b1; v[5] = b2; v[7] = b3;
}

// ---------------- HMMA helpers ----------------
__device__ __forceinline__ uint32_t smem_u32(const void* p) {
    uint32_t a;
    asm("{ .reg .u64 t; cvta.to.shared.u64 t, %1; cvt.u32.u64 %0, t; }" : "=r"(a) : "l"(p));
    return a;
}
__device__ __forceinline__ void ldmA(unsigned r[4], uint32_t addr) {
    asm volatile("ldmatrix.sync.aligned.m8n8.x4.shared.b16 {%0,%1,%2,%3}, [%4];"
        : "=r"(r[0]),"=r"(r[1]),"=r"(r[2]),"=r"(r[3]) : "r"(addr));
}
__device__ __forceinline__ void mma16816(float d[4], const unsigned a[4], const unsigned b[2]) {
    asm volatile("mma.sync.aligned.m16n8k16.row.col.f32.bf16.bf16.f32 "
        "{%0,%1,%2,%3}, {%4,%5,%6,%7}, {%8,%9}, {%0,%1,%2,%3};"
        : "+f"(d[0]),"+f"(d[1]),"+f"(d[2]),"+f"(d[3])
        : "r"(a[0]),"r"(a[1]),"r"(a[2]),"r"(a[3]), "r"(b[0]),"r"(b[1]));
}

// ---------------- prep: twiddles + bf16 weight transposition ----------------
__global__ void kPrep(const float* __restrict__ w1, const float* __restrict__ w2)
{
    int t = blockIdx.x * blockDim.x + threadIdx.x;
    const double TP = 6.283185307179586476925286766559;
    if (t < 768) {
        double s, c;
        sincos(-TP * (double)t / 768.0, &s, &c);
        g_tw768[t] = make_float2((float)c, (float)s);
        if (t < 256) { sincos(-TP*(double)t/256.0, &s, &c); g_tw256[t] = make_float2((float)c,(float)s); }
        if (t < 128) { sincos(-TP*(double)t/128.0, &s, &c); g_tw128[t] = make_float2((float)c,(float)s); }
    }
    int stride = gridDim.x * blockDim.x;
    for (int e = t; e < 4*NB*BS*BS; e += stride) {
        int m = e / (NB*BS*BS);
        int r = e - m*(NB*BS*BS);
        int n = r / (BS*BS);
        int q = r - n*(BS*BS);
        int i = q / BS, o = q - i*BS;
        const float* src = (m < 2) ? (w1 + (size_t)(m*NB + n)*9216)
                                   : (w2 + (size_t)((m-2)*NB + n)*9216);
        g_Wb[m][n][o*WSTR + i] = __float2bfloat16(src[i*96 + o]);
    }
}

// ---------------- forward W-FFT (256=16x16) pruned kw<65 + an emit : x -> g_A, g_C ----------------
__global__ __launch_bounds__(256) void kF1(const float* __restrict__ x)
{
    extern __shared__ float smF1[];
    float*  Xs  = smF1;
    float2* Ys  = (float2*)(smF1 + 4352);
    float2* stw = Ys + 4352;
    const int bh = blockIdx.x, c0 = blockIdx.y * 16, tid = threadIdx.x;
    if (tid < 256) stw[tid] = g_tw256[tid];
    const float* xp = x + (size_t)bh * (WW*CCH) + c0;
    for (int e = tid; e < 4096; e += 256)
        Xs[(e >> 4)*17 + (e & 15)] = xp[(size_t)(e >> 4) * CCH + (e & 15)];
    __syncthreads();
    {
        const int b = bh >> 7, h = bh & 127;
        const int hn = (HH - h) & (HH - 1);
        __nv_bfloat16* cp = g_C + (((size_t)b*HH + hn)*KWV)*CCH + c0;
        for (int e = tid; e < KWV*16; e += 256) {
            int kw = e >> 4, c = e & 15;
            int wn = (WW - kw) & (WW - 1);
            cp[(size_t)kw*CCH + c] = __float2bfloat16(Xs[wn*17 + c]);
        }
    }
    {
        const int n2 = tid >> 4, c = tid & 15;
        float2 u[16];
        #pragma unroll
        for (int n1 = 0; n1 < 16; n1++) u[n1] = make_float2(Xs[(16*n1 + n2)*17 + c], 0.f);
        fft16r(u);
        #pragma unroll
        for (int k1 = 0; k1 < 16; k1++)
            Ys[(k1*16 + n2)*17 + c] = cmul(u[FFI(k1)], stw[n2*k1]);
    }
    __syncthreads();
    {
        const int k1 = tid >> 4, c = tid & 15;
        float2 v[16];
        #pragma unroll
        for (int n2 = 0; n2 < 16; n2++) v[n2] = Ys[(k1*16 + n2)*17 + c];
        fft16r(v);
        cbf* dst = g_A + ((size_t)bh*KWV)*CCH + c0 + c;
        #pragma unroll
        for (int k2 = 0; k2 < 4; k2++)
            dst[(size_t)(k1 + 16*k2)*CCH] = f2b(v[FFI(k2)]);
        if (k1 == 0)
            dst[(size_t)64*CCH] = f2b(v[FFI(4)]);
    }
}

// ---------------- C-FFT 768 = 16x16x3 : RIN=0: g_A->g_B; RIN=1: real(bf16) g_B->g_A ----------------
template<int RIN>
__global__ __launch_bounds__(192) void kFC()
{
    extern __shared__ char smCb[];
    cbf*    zb     = (cbf*)smCb;
    float2* Ab     = (float2*)(smCb + 12288);
    float2* stw256 = (float2*)(smCb + 36864);
    float2* stw768 = (float2*)(smCb + 38912);
    const int tid = threadIdx.x;
    const int r = tid / 48, l = tid - r*48;
    const size_t row0 = (size_t)blockIdx.x * 4;
    for (int e = tid; e < 256; e += 192) stw256[e] = g_tw256[e];
    for (int e = tid; e < 512; e += 192) stw768[e] = g_tw768[e];
    if (RIN) {
        const __nv_bfloat16* sp = (const __nv_bfloat16*)g_B;
        for (int e = tid; e < 3072; e += 192) {
            cbf z; z.x = sp[row0*768 + e]; z.y = __float2bfloat16(0.f);
            zb[e] = z;
        }
    } else {
        const uint4* sp = (const uint4*)(g_A + row0*768);
        uint4* dp = (uint4*)zb;
        for (int e = tid; e < 768; e += 192)
            dp[e] = sp[e];
    }
    __syncthreads();
    {
        const int n3 = l >> 4, n2 = l & 15;
        float2 u[16];
        #pragma unroll
        for (int n1 = 0; n1 < 16; n1++) u[n1] = b2f(zb[r*768 + n3 + 3*n2 + 48*n1]);
        fft16r(u);
        #pragma unroll
        for (int k1 = 0; k1 < 16; k1++)
            Ab[r*768 + (n3*16 + k1)*16 + n2] = cmul(u[FFI(k1)], stw256[n2*k1]);
    }
    __syncthreads();
    {
        const int n3 = l >> 4, k1 = l & 15;
        float2 v[16];
        #pragma unroll
        for (int n2 = 0; n2 < 16; n2++) v[n2] = Ab[r*768 + (n3*16 + k1)*16 + n2];
        fft16r(v);
        #pragma unroll
        for (int k2 = 0; k2 < 16; k2++)
            zb[r*768 + (n3*16 + k1)*16 + k2] = f2b(v[FFI(k2)]);
    }
    __syncthreads();
    {
        cbf* dst = RIN ? g_A : g_B;
        const float s3 = 0.86602540378443865f;
        for (int e = tid; e < 1024; e += 192) {
            const int rr = e >> 8, m = e & 255;
            const int k1 = m & 15, k2 = m >> 4;
            float2 b0 = b2f(zb[rr*768 +       k1*16 + k2]);
            float2 b1 = cmul(b2f(zb[rr*768 + 256 + k1*16 + k2]), stw768[m]);
            float2 b2 = cmul(b2f(zb[rr*768 + 512 + k1*16 + k2]), stw768[2*m]);
            float2 t1 = make_float2(b1.x + b2.x, b1.y + b2.y);
            float2 t2 = make_float2(b1.x - b2.x, b1.y - b2.y);
            dst[(row0+rr)*768 + m] = f2b(make_float2(b0.x + t1.x, b0.y + t1.y));
            float xr = fmaf(-0.5f, t1.x, b0.x);
            float xi = fmaf(-0.5f, t1.y, b0.y);
            dst[(row0+rr)*768 + m + 256] = f2b(make_float2(fmaf( s3, t2.y, xr), fmaf(-s3, t2.x, xi)));
            dst[(row0+rr)*768 + m + 512] = f2b(make_float2(fmaf(-s3, t2.y, xr), fmaf( s3, t2.x, xi)));
        }
    }
}

// ---------------- H-FFT (128=16x8) + B-FFT.  FWD=1: g_B -> av (real bf16) in g_A ; FWD=0: g_A -> g_B ----------------
template<int FWD>
__global__ __launch_bounds__(256) void kFHB()
{
    __shared__ float2 Ys[2][16][8][16];
    __shared__ float2 stw[128];
    const cbf* __restrict__ src = FWD ? g_B : g_A;
    const int kw = blockIdx.x, c0 = blockIdx.y * 16, tid = threadIdx.x;
    if (tid < 128) stw[tid] = g_tw128[tid];
    {
        const int c = tid & 15, n2 = (tid >> 4) & 7, bb = tid >> 7;
        const size_t hstep = (size_t)8 * KWV * CCH;
        const cbf* p0 = src + ((size_t)n2 * KWV + kw)*CCH + c0 + c;
        const cbf* p1 = p0 + (size_t)HH * KWV * CCH;
        float2 u[16];
        #pragma unroll
        for (int n1 = 0; n1 < 16; n1++) {
            float2 a = b2f(*p0), b = b2f(*p1);
            p0 += hstep; p1 += hstep;
            u[n1] = bb ? make_float2(a.x - b.x, a.y - b.y)
                       : make_float2(a.x + b.x, a.y + b.y);
        }
        __syncthreads();
        fft16r(u);
        #pragma unroll
        for (int k1 = 0; k1 < 16; k1++)
            Ys[bb][k1][n2][c] = cmul(u[FFI(k1)], stw[k1*n2]);
    }
    __syncthreads();
    #pragma unroll
    for (int r = 0; r < 2; r++) {
        int t = tid + 256*r;
        int c = t & 15, k1 = (t >> 4) & 15, bb = t >> 8;
        float2 v[8];
        #pragma unroll
        for (int n2 = 0; n2 < 8; n2++) v[n2] = Ys[bb][k1][n2][c];
        fft8r(v);
        const size_t kstep = (size_t)16 * KWV * CCH;
        const size_t base = (((size_t)bb*HH + k1)*KWV + kw)*CCH + c0 + c;
        if (FWD) {
            // av emit only (real bf16); S/D formed later in kMLP
            __nv_bfloat16* q = (__nv_bfloat16*)g_A + base;
            #pragma unroll
            for (int k2 = 0; k2 < 8; k2++) {
                *q = __float2bfloat16(v[k2].x + v[k2].y);
                q += kstep;
            }
        } else {
            cbf* q = g_B + base;
            #pragma unroll
            for (int k2 = 0; k2 < 8; k2++) {
                *q = f2b(v[k2]);
                q += kstep;
            }
        }
    }
}

// ---------------- HMMA MLP: g_A(av) + g_C(an) -> s (bf16) in g_B ----------------
#define MO_AS 0
#define MO_AD 26624
#define MO_W0 53248
#define MO_W1 73216
#define MSM   93184
#define ASTR  104
#define SOP   133

__device__ __forceinline__ void mmaGemv(uint32_t aSb, uint32_t aDb,
    const __nv_bfloat16* __restrict__ w0, const __nv_bfloat16* __restrict__ w1v,
    int warpM, int warpN, int lane, int g, int tig,
    float U[2][3][4], float V[2][3][4])
{
    #pragma unroll
    for (int mi = 0; mi < 2; mi++)
        #pragma unroll
        for (int ni = 0; ni < 3; ni++)
            #pragma unroll
            for (int j = 0; j < 4; j++) { U[mi][ni][j] = 0.f; V[mi][ni][j] = 0.f; }
    const uint32_t lrow = (uint32_t)(lane & 15) * (ASTR*2);
    const uint32_t lcol = (uint32_t)((lane >> 4) << 4);
    #pragma unroll
    for (int kb = 0; kb < 6; kb++) {
        const int kc = kb * 16;
        unsigned aS0[4], aS1[4], aD0[4], aD1[4];
        uint32_t base = lrow + lcol + kc*2;
        ldmA(aS0, aSb + (uint32_t)(warpM*32     )*(ASTR*2) + base);
        ldmA(aS1, aSb + (uint32_t)(warpM*32 + 16)*(ASTR*2) + base);
        ldmA(aD0, aDb + (uint32_t)(warpM*32     )*(ASTR*2) + base);
        ldmA(aD1, aDb + (uint32_t)(warpM*32 + 16)*(ASTR*2) + base);
        #pragma unroll
        for (int ni = 0; ni < 3; ni++) {
            const int orow = warpN*24 + ni*8 + g;
            unsigned b0[2], b1[2];
            b0[0] = *(const unsigned*)&w0 [orow*WSTR + kc + 2*tig];
            b0[1] = *(const unsigned*)&w0 [orow*WSTR + kc + 8 + 2*tig];
            b1[0] = *(const unsigned*)&w1v[orow*WSTR + kc + 2*tig];
            b1[1] = *(const unsigned*)&w1v[orow*WSTR + kc + 8 + 2*tig];
            mma16816(U[0][ni], aS0, b0);
            mma16816(U[1][ni], aS1, b0);
            mma16816(V[0][ni], aD0, b1);
            mma16816(V[1][ni], aD1, b1);
        }
    }
}

__global__ __launch_bounds__(512, 1) void kMLP(const float* __restrict__ b1,
                                               const float* __restrict__ b2)
{
    extern __shared__ char smc[];
    __nv_bfloat16* aS  = (__nv_bfloat16*)(smc + MO_AS);
    __nv_bfloat16* aD  = (__nv_bfloat16*)(smc + MO_AD);
    __nv_bfloat16* wS0 = (__nv_bfloat16*)(smc + MO_W0);
    __nv_bfloat16* wS1 = (__nv_bfloat16*)(smc + MO_W1);
    const uint32_t aSb = smem_u32(aS), aDb = smem_u32(aD);
    const int n = blockIdx.y, p0 = blockIdx.x * 128, tid = threadIdx.x;
    const int wid = tid >> 5, lane = tid & 31;
    const int warpM = wid >> 2, warpN = wid & 3;
    const int g = lane >> 2, tig = lane & 3;

    {
        const uint4* s0 = (const uint4*)g_Wb[0][n];
        const uint4* s1 = (const uint4*)g_Wb[1][n];
        for (int e = tid; e < (BS*WSTR)/8; e += 512) {
            ((uint4*)wS0)[e] = s0[e];
            ((uint4*)wS1)[e] = s1[e];
        }
    }
    // activation staging: coalesced av/an loads (bf16x2), form S/D inline
    {
        const __nv_bfloat16* gAv = (const __nv_bfloat16*)g_A + (size_t)p0*CCH + n*BS;
        const __nv_bfloat16* gAn = g_C + (size_t)p0*CCH + n*BS;
        for (int e = tid; e < 6144; e += 512) {
            int p = e / 48, c = (e - 48*p) * 2;
            float2 av = b2f(*(const cbf*)&gAv[(size_t)p*CCH + c]);
            float2 an = b2f(*(const cbf*)&gAn[(size_t)p*CCH + c]);
            *(cbf*)&aS[p*ASTR + c] = f2b(make_float2(av.x + an.x, av.y + an.y));
            *(cbf*)&aD[p*ASTR + c] = f2b(make_float2(av.x - an.x, av.y - an.y));
        }
    }
    __syncthreads();

    float U[2][3][4], V[2][3][4], keep[2][3][4];

    // ===== layer 1 =====
    mmaGemv(aSb, aDb, wS0, wS1, warpM, warpN, lane, g, tig, U, V);
    __syncthreads();
    #pragma unroll
    for (int mi = 0; mi < 2; mi++)
        #pragma unroll
        for (int ni = 0; ni < 3; ni++) {
            const int o = warpN*24 + ni*8 + 2*tig;
            const float bk0 = b1[n*BS + o],        bk1 = b1[n*BS + o + 1];
            const float bn0 = b1[(NB+n)*BS + o],   bn1 = b1[(NB+n)*BS + o + 1];
            const int p = warpM*32 + mi*16 + g;
            #pragma unroll
            for (int hh = 0; hh < 2; hh++) {
                float Uu0 = U[mi][ni][2*hh], Uu1 = U[mi][ni][2*hh+1];
                float Vv0 = V[mi][ni][2*hh], Vv1 = V[mi][ni][2*hh+1];
                float k0 = fmaxf(fmaf(0.5f, Uu0 + Vv0, bk0), 0.f);
                float n0 = fmaxf(fmaf(0.5f, Uu0 - Vv0, bn0), 0.f);
                float k1 = fmaxf(fmaf(0.5f, Uu1 + Vv1, bk1), 0.f);
                float n1 = fmaxf(fmaf(0.5f, Uu1 - Vv1, bn1), 0.f);
                keep[mi][ni][2*hh] = n0; keep[mi][ni][2*hh+1] = n1;
                const int pp = p + 8*hh;
                *(__nv_bfloat162*)&aS[pp*ASTR + o] = __floats2bfloat162_rn(k0 + n0, k1 + n1);
                *(__nv_bfloat162*)&aD[pp*ASTR + o] = __floats2bfloat162_rn(k0 - n0, k1 - n1);
            }
        }
    {
        const uint4* s0 = (const uint4*)g_Wb[2][n];
        const uint4* s1 = (const uint4*)g_Wb[3][n];
        for (int e = tid; e < (BS*WSTR)/8; e += 512) {
            ((uint4*)wS0)[e] = s0[e];
            ((uint4*)wS1)[e] = s1[e];
        }
    }
    __syncthreads();

    // ===== layer 2 (o2_k) =====
    mmaGemv(aSb, aDb, wS0, wS1, warpM, warpN, lane, g, tig, U, V);
    __syncthreads();
    #pragma unroll
    for (int mi = 0; mi < 2; mi++)
        #pragma unroll
        for (int ni = 0; ni < 3; ni++) {
            const int o = warpN*24 + ni*8 + 2*tig;
            const float bk0 = b2[n*BS + o], bk1 = b2[n*BS + o + 1];
            const int p = warpM*32 + mi*16 + g;
            #pragma unroll
            for (int hh = 0; hh < 2; hh++) {
                float ok0 = fmaf(0.5f, U[mi][ni][2*hh]   + V[mi][ni][2*hh],   bk0);
                float ok1 = fmaf(0.5f, U[mi][ni][2*hh+1] + V[mi][ni][2*hh+1], bk1);
                float un0 = keep[mi][ni][2*hh], un1 = keep[mi][ni][2*hh+1];
                keep[mi][ni][2*hh] = ok0; keep[mi][ni][2*hh+1] = ok1;
                const int pp = p + 8*hh;
                *(__nv_bfloat162*)&aS[pp*ASTR + o] = __floats2bfloat162_rn(un0 + ok0, un1 + ok1);
                *(__nv_bfloat162*)&aD[pp*ASTR + o] = __floats2bfloat162_rn(un0 - ok0, un1 - ok1);  // o2_nk uses o2_k
            }
        }
    __syncthreads();

    // ===== layer 2 (o2_nk) + soft-threshold =====
    mmaGemv(aSb, aDb, wS0, wS1, warpM, warpN, lane, g, tig, U, V);
    __syncthreads();
    float* sOut = (float*)(smc + MO_AS);
    #pragma unroll
    for (int mi = 0; mi < 2; mi++)
        #pragma unroll
        for (int ni = 0; ni < 3; ni++) {
            const int o = warpN*24 + ni*8 + 2*tig;
            const float bn0 = b2[(NB+n)*BS + o], bn1 = b2[(NB+n)*BS + o + 1];
            const int p = warpM*32 + mi*16 + g;
            #pragma unroll
            for (int hh = 0; hh < 2; hh++) {
                float o2n0 = fmaf(0.5f, U[mi][ni][2*hh]   + V[mi][ni][2*hh],   bn0);
                float o2n1 = fmaf(0.5f, U[mi][ni][2*hh+1] + V[mi][ni][2*hh+1], bn1);
                float t0 = keep[mi][ni][2*hh]   + o2n0;
                float t1 = keep[mi][ni][2*hh+1] + o2n1;
                const int pp = p + 8*hh;
                sOut[o*SOP + pp]     = copysignf(fmaxf(fabsf(t0) - 0.01f, 0.f), t0);
                sOut[(o+1)*SOP + pp] = copysignf(fmaxf(fabsf(t1) - 0.01f, 0.f), t1);
            }
        }
    __syncthreads();
    __nv_bfloat16* outp = (__nv_bfloat16*)g_B;
    for (int e = tid; e < 12288; e += 512) {
        int p = e / 96, c = e - 96*p;
        outp[(size_t)(p0 + p)*CCH + n*BS + c] = __float2bfloat16(sOut[c*SOP + p]);
    }
}

// ---------------- inverse W-FFT (65 -> 256) + scale + residual : g_B -> out ----------------
__global__ __launch_bounds__(256) void kIW(const float* __restrict__ x, float* __restrict__ out)
{
    __shared__ float2 Zs[KWV*16];
    __shared__ float2 Ys[256*17];
    __shared__ float2 stw[256];
    const int bh = blockIdx.x, c0 = blockIdx.y * 16, tid = threadIdx.x;
    if (tid < 256) stw[tid] = g_tw256[tid];
    const cbf* __restrict__ zp = g_B + (size_t)bh*KWV*CCH + c0;
    for (int e = tid; e < KWV*16; e += 256) {
        int w = e >> 4, c = e & 15;
        Zs[e] = b2f(zp[(size_t)w*CCH + c]);
    }
    __syncthreads();
    for (int e = tid; e < 4096; e += 256) {
        int c = e & 15, n2 = (e >> 4) & 15, k1 = e >> 8;
        float2 acc = make_float2(0.f, 0.f);
        int idx = (k1 * n2) & 255, step = (k1 * 16) & 255;
        int nmax = (n2 == 0) ? 5 : 4;
        for (int n1 = 0; n1 < nmax; n1++) {
            int w = (n1 << 4) + n2;
            cmadd(acc, Zs[w*16 + c], stw[idx]);
            idx = (idx + step) & 255;
        }
        Ys[(k1*16 + n2)*17 + c] = acc;
    }
    __syncthreads();
    const float invN = 1.0f / 50331648.0f;
    {
        const int k1 = tid >> 4, c = tid & 15;
        float2 v[16];
        #pragma unroll
        for (int n2 = 0; n2 < 16; n2++) v[n2] = Ys[(k1*16 + n2)*17 + c];
        fft16r(v);
        #pragma unroll
        for (int k2 = 0; k2 < 16; k2++) {
            float2 acc = v[FFI(k2)];
            size_t a = ((size_t)bh*WW + k1 + 16*k2)*CCH + c0 + c;
            out[a] = fmaf(acc.x + acc.y, invN, x[a]);
        }
    }
}

extern "C" void kernel_launch(void* const* d_in, const int* in_sizes, int n_in,
                              void* d_out, int out_size)
{
    const float* x  = (const float*)d_in[0];
    const float* w1 = (const float*)d_in[1];
    const float* b1 = (const float*)d_in[2];
    const float* w2 = (const float*)d_in[3];
    const float* b2 = (const float*)d_in[4];
    float* out = (float*)d_out;

    cudaFuncSetAttribute(kMLP,   cudaFuncAttributeMaxDynamicSharedMemorySize, MSM);
    cudaFuncSetAttribute(kF1,    cudaFuncAttributeMaxDynamicSharedMemorySize, 54272);
    cudaFuncSetAttribute(kFC<0>, cudaFuncAttributeMaxDynamicSharedMemorySize, 43008);
    cudaFuncSetAttribute(kFC<1>, cudaFuncAttributeMaxDynamicSharedMemorySize, 43008);

    kPrep<<<290, 1024>>>(w1, w2);
    kF1 <<<dim3(BB*HH, CCH/16), 256, 54272>>>(x);   // x -> A (cplx) + C (an)
    kFC<0><<<NPOS/4, 192, 43008>>>();               // A -> B
    kFHB<1><<<dim3(KWV, CCH/16), 256>>>();          // B -> av (real bf16) in A
    kMLP<<<dim3(NPOS/128, NB), 512, MSM>>>(b1, b2); // A(av)+C(an) -> s(bf16) in B
    kFC<1><<<NPOS/4, 192, 43008>>>();               // B(real bf16) -> A
    kFHB<0><<<dim3(KWV, CCH/16), 256>>>();          // A -> B
    kIW <<<dim3(BB*HH, CCH/16), 256>>>(x, out);     // B -> out
}

// round 16
// speedup vs baseline: 1.2320x; 1.2063x over previous
#include <cuda_runtime.h>
#include <cuda_bf16.h>
#include <math.h>
#include <stdint.h>

#define BB 2
#define HH 128
#define WW 256
#define CCH 768
#define KWV 65
#define NB 8
#define BS 96
#define NPOS (BB*HH*KWV)
#define SLABN (NPOS*CCH)

typedef unsigned long long u64;
typedef __nv_bfloat162 cbf;

__device__ cbf g_A[SLABN];                 // 51 MB: complex slab / av real slab (bf16)
__device__ cbf g_B[SLABN];                 // 51 MB
__device__ __nv_bfloat16 g_C[SLABN];       // 25.5 MB: an gather slab (real bf16)
__device__ float2 g_tw256[256];
__device__ float2 g_tw768[768];
__device__ float2 g_tw128[128];

#define WSTR 104
__device__ __nv_bfloat16 g_Wb[4][NB][BS*WSTR];   // pre-transposed bf16 weights [o][i]

__device__ __forceinline__ float2 b2f(cbf v) {
    return make_float2(__bfloat162float(v.x), __bfloat162float(v.y));
}
__device__ __forceinline__ cbf f2b(float2 v) {
    return __floats2bfloat162_rn(v.x, v.y);
}
__device__ __forceinline__ void cmadd(float2& acc, float2 z, float2 t) {
    acc.x = fmaf(z.x, t.x, fmaf(-z.y, t.y, acc.x));
    acc.y = fmaf(z.x, t.y, fmaf( z.y, t.x, acc.y));
}
__device__ __forceinline__ float2 cmul(float2 a, float2 b) {
    return make_float2(a.x*b.x - a.y*b.y, a.x*b.y + a.y*b.x);
}

// ---------------- register FFT primitives ----------------
#define FC1 0.92387953251128674f
#define FS1 0.38268343236508977f
#define FR  0.70710678118654752f

__device__ __forceinline__ float2 cadd2(float2 a, float2 b) {
    return make_float2(fmaf(b.x, 1.0f, a.x), fmaf(b.y, 1.0f, a.y));
}
__device__ __forceinline__ float2 csub2(float2 a, float2 b) {
    return make_float2(fmaf(b.x, -1.0f, a.x), fmaf(b.y, -1.0f, a.y));
}
__device__ __forceinline__ float2 cmulK(float2 z, float C, float S) {
    return make_float2(fmaf(z.x, C, -z.y*S), fmaf(z.y, C, z.x*S));
}
__device__ __forceinline__ void dft4(float2& a, float2& b, float2& c, float2& d) {
    float2 apc = cadd2(a, c), amc = csub2(a, c);
    float2 bpd = cadd2(b, d), bmd = csub2(b, d);
    float2 jb = make_float2(bmd.y, -bmd.x);
    a = cadd2(apc, bpd);
    b = cadd2(amc, jb);
    c = csub2(apc, bpd);
    d = csub2(amc, jb);
}
#define FFI(k) (4*((k)&3) + ((k)>>2))
__device__ __forceinline__ void fft16r(float2 v[16]) {
    dft4(v[0], v[4], v[8],  v[12]);
    dft4(v[1], v[5], v[9],  v[13]);
    dft4(v[2], v[6], v[10], v[14]);
    dft4(v[3], v[7], v[11], v[15]);
    v[5]  = cmulK(v[5],  FC1, -FS1);
    v[6]  = cmulK(v[6],  FR,  -FR );
    v[7]  = cmulK(v[7],  FS1, -FC1);
    v[9]  = cmulK(v[9],  FR,  -FR );
    v[10] = make_float2(v[10].y, -v[10].x);
    v[11] = cmulK(v[11], -FR,  -FR );
    v[13] = cmulK(v[13], FS1, -FC1);
    v[14] = cmulK(v[14], -FR,  -FR );
    v[15] = cmulK(v[15], -FC1,  FS1);
    dft4(v[0],  v[1],  v[2],  v[3]);
    dft4(v[4],  v[5],  v[6],  v[7]);
    dft4(v[8],  v[9],  v[10], v[11]);
    dft4(v[12], v[13], v[14], v[15]);
}
__device__ __forceinline__ void fft8r(float2 v[8]) {
    float2 a0 = cadd2(v[0], v[4]), a1 = cadd2(v[1], v[5]);
    float2 a2 = cadd2(v[2], v[6]), a3 = cadd2(v[3], v[7]);
    float2 b0 = csub2(v[0], v[4]);
    float2 t1 = csub2(v[1], v[5]);
    float2 t2 = csub2(v[2], v[6]);
    float2 t3 = csub2(v[3], v[7]);
    float2 b1 = cmulK(t1, FR, -FR);
    float2 b2 = make_float2(t2.y, -t2.x);
    float2 b3 = cmulK(t3, -FR, -FR);
    dft4(a0, a1, a2, a3);
    dft4(b0, b1, b2, b3);
    v[0] = a0; v[2] = a1; v[4] = a2; v[6] = a3;
    v[1] = b0; v[3] = b1; v[5] = b2; v[7] = b3;
}

// ---------------- HMMA helpers ----------------
__device__ __forceinline__ uint32_t smem_u32(const void* p) {
    uint32_t a;
    asm("{ .reg .u64 t; cvta.to.shared.u64 t, %1; cvt.u32.u64 %0, t; }" : "=r"(a) : "l"(p));
    return a;
}
__device__ __forceinline__ void ldmA(unsigned r[4], uint32_t addr) {
    asm volatile("ldmatrix.sync.aligned.m8n8.x4.shared.b16 {%0,%1,%2,%3}, [%4];"
        : "=r"(r[0]),"=r"(r[1]),"=r"(r[2]),"=r"(r[3]) : "r"(addr));
}
__device__ __forceinline__ void mma16816(float d[4], const unsigned a[4], const unsigned b[2]) {
    asm volatile("mma.sync.aligned.m16n8k16.row.col.f32.bf16.bf16.f32 "
        "{%0,%1,%2,%3}, {%4,%5,%6,%7}, {%8,%9}, {%0,%1,%2,%3};"
        : "+f"(d[0]),"+f"(d[1]),"+f"(d[2]),"+f"(d[3])
        : "r"(a[0]),"r"(a[1]),"r"(a[2]),"r"(a[3]), "r"(b[0]),"r"(b[1]));
}

// ---------------- prep: twiddles + bf16 weight transposition ----------------
__global__ void kPrep(const float* __restrict__ w1, const float* __restrict__ w2)
{
    int t = blockIdx.x * blockDim.x + threadIdx.x;
    const double TP = 6.283185307179586476925286766559;
    if (t < 768) {
        double s, c;
        sincos(-TP * (double)t / 768.0, &s, &c);
        g_tw768[t] = make_float2((float)c, (float)s);
        if (t < 256) { sincos(-TP*(double)t/256.0, &s, &c); g_tw256[t] = make_float2((float)c,(float)s); }
        if (t < 128) { sincos(-TP*(double)t/128.0, &s, &c); g_tw128[t] = make_float2((float)c,(float)s); }
    }
    int stride = gridDim.x * blockDim.x;
    for (int e = t; e < 4*NB*BS*BS; e += stride) {
        int m = e / (NB*BS*BS);
        int r = e - m*(NB*BS*BS);
        int n = r / (BS*BS);
        int q = r - n*(BS*BS);
        int i = q / BS, o = q - i*BS;
        const float* src = (m < 2) ? (w1 + (size_t)(m*NB + n)*9216)
                                   : (w2 + (size_t)((m-2)*NB + n)*9216);
        g_Wb[m][n][o*WSTR + i] = __float2bfloat16(src[i*96 + o]);
    }
}

// ---------------- forward W-FFT (256=16x16) pruned kw<65 + an emit : x -> g_A, g_C ----------------
__global__ __launch_bounds__(256) void kF1(const float* __restrict__ x)
{
    extern __shared__ float smF1[];
    float*  Xs  = smF1;
    float2* Ys  = (float2*)(smF1 + 4352);
    float2* stw = Ys + 4352;
    const int bh = blockIdx.x, c0 = blockIdx.y * 16, tid = threadIdx.x;
    if (tid < 256) stw[tid] = g_tw256[tid];
    const float* xp = x + (size_t)bh * (WW*CCH) + c0;
    for (int e = tid; e < 1024; e += 256) {
        int w = e >> 2, c4 = (e & 3) * 4;
        float4 v = *(const float4*)(xp + (size_t)w * CCH + c4);
        Xs[w*17 + c4]     = v.x;
        Xs[w*17 + c4 + 1] = v.y;
        Xs[w*17 + c4 + 2] = v.z;
        Xs[w*17 + c4 + 3] = v.w;
    }
    __syncthreads();
    {
        const int b = bh >> 7, h = bh & 127;
        const int hn = (HH - h) & (HH - 1);
        __nv_bfloat16* cp = g_C + (((size_t)b*HH + hn)*KWV)*CCH + c0;
        for (int e = tid; e < KWV*8; e += 256) {
            int kw = e >> 3, c = (e & 7) * 2;
            int wn = (WW - kw) & (WW - 1);
            *(cbf*)&cp[(size_t)kw*CCH + c] =
                __floats2bfloat162_rn(Xs[wn*17 + c], Xs[wn*17 + c + 1]);
        }
    }
    {
        const int n2 = tid >> 4, c = tid & 15;
        float2 u[16];
        #pragma unroll
        for (int n1 = 0; n1 < 16; n1++) u[n1] = make_float2(Xs[(16*n1 + n2)*17 + c], 0.f);
        fft16r(u);
        #pragma unroll
        for (int k1 = 0; k1 < 16; k1++)
            Ys[(k1*16 + n2)*17 + c] = cmul(u[FFI(k1)], stw[n2*k1]);
    }
    __syncthreads();
    {
        const int k1 = tid >> 4, c = tid & 15;
        float2 v[16];
        #pragma unroll
        for (int n2 = 0; n2 < 16; n2++) v[n2] = Ys[(k1*16 + n2)*17 + c];
        fft16r(v);
        cbf* dst = g_A + ((size_t)bh*KWV)*CCH + c0 + c;
        #pragma unroll
        for (int k2 = 0; k2 < 4; k2++)
            dst[(size_t)(k1 + 16*k2)*CCH] = f2b(v[FFI(k2)]);
        if (k1 == 0)
            dst[(size_t)64*CCH] = f2b(v[FFI(4)]);
    }
}

// ---------------- C-FFT 768 = 16x16x3 (bf16 intermediates, 30.7KB smem) ----------------
// RIN=0: g_A->g_B; RIN=1: real(bf16) g_B->g_A
template<int RIN>
__global__ __launch_bounds__(192) void kFC()
{
    extern __shared__ char smCb[];
    cbf* zb      = (cbf*)smCb;                   // 4*768 cbf = 12288B
    cbf* Ab      = (cbf*)(smCb + 12288);         // 4*768 cbf = 12288B
    float2* stw256 = (float2*)(smCb + 24576);    // 2048B
    float2* stw768 = (float2*)(smCb + 26624);    // 4096B  -> total 30720B
    const int tid = threadIdx.x;
    const int r = tid / 48, l = tid - r*48;
    const size_t row0 = (size_t)blockIdx.x * 4;
    for (int e = tid; e < 256; e += 192) stw256[e] = g_tw256[e];
    for (int e = tid; e < 512; e += 192) stw768[e] = g_tw768[e];
    if (RIN) {
        const __nv_bfloat16* sp = (const __nv_bfloat16*)g_B;
        for (int e = tid; e < 3072; e += 192) {
            cbf z; z.x = sp[row0*768 + e]; z.y = __float2bfloat16(0.f);
            zb[e] = z;
        }
    } else {
        const uint4* sp = (const uint4*)(g_A + row0*768);
        uint4* dp = (uint4*)zb;
        for (int e = tid; e < 768; e += 192)
            dp[e] = sp[e];
    }
    __syncthreads();
    {
        const int n3 = l >> 4, n2 = l & 15;
        float2 u[16];
        #pragma unroll
        for (int n1 = 0; n1 < 16; n1++) u[n1] = b2f(zb[r*768 + n3 + 3*n2 + 48*n1]);
        fft16r(u);
        #pragma unroll
        for (int k1 = 0; k1 < 16; k1++)
            Ab[r*768 + (n3*16 + k1)*16 + n2] = f2b(cmul(u[FFI(k1)], stw256[n2*k1]));
    }
    __syncthreads();
    {
        const int n3 = l >> 4, k1 = l & 15;
        float2 v[16];
        #pragma unroll
        for (int n2 = 0; n2 < 16; n2++) v[n2] = b2f(Ab[r*768 + (n3*16 + k1)*16 + n2]);
        fft16r(v);
        #pragma unroll
        for (int k2 = 0; k2 < 16; k2++)
            zb[r*768 + (n3*16 + k1)*16 + k2] = f2b(v[FFI(k2)]);
    }
    __syncthreads();
    {
        cbf* dst = RIN ? g_A : g_B;
        const float s3 = 0.86602540378443865f;
        for (int e = tid; e < 1024; e += 192) {
            const int rr = e >> 8, m = e & 255;
            const int k1 = m & 15, k2 = m >> 4;
            float2 b0 = b2f(zb[rr*768 +       k1*16 + k2]);
            float2 b1 = cmul(b2f(zb[rr*768 + 256 + k1*16 + k2]), stw768[m]);
            float2 b2 = cmul(b2f(zb[rr*768 + 512 + k1*16 + k2]), stw768[2*m]);
            float2 t1 = make_float2(b1.x + b2.x, b1.y + b2.y);
            float2 t2 = make_float2(b1.x - b2.x, b1.y - b2.y);
            dst[(row0+rr)*768 + m] = f2b(make_float2(b0.x + t1.x, b0.y + t1.y));
            float xr = fmaf(-0.5f, t1.x, b0.x);
            float xi = fmaf(-0.5f, t1.y, b0.y);
            dst[(row0+rr)*768 + m + 256] = f2b(make_float2(fmaf( s3, t2.y, xr), fmaf(-s3, t2.x, xi)));
            dst[(row0+rr)*768 + m + 512] = f2b(make_float2(fmaf(-s3, t2.y, xr), fmaf( s3, t2.x, xi)));
        }
    }
}

// ---------------- H-FFT (128=16x8) + B-FFT.  FWD=1: g_B -> av (real bf16) in g_A ; FWD=0: g_A -> g_B ----------------
template<int FWD>
__global__ __launch_bounds__(256) void kFHB()
{
    __shared__ float2 Ys[2][16][8][16];
    __shared__ float2 stw[128];
    const cbf* __restrict__ src = FWD ? g_B : g_A;
    const int kw = blockIdx.x, c0 = blockIdx.y * 16, tid = threadIdx.x;
    if (tid < 128) stw[tid] = g_tw128[tid];
    {
        const int c = tid & 15, n2 = (tid >> 4) & 7, bb = tid >> 7;
        const size_t hstep = (size_t)8 * KWV * CCH;
        const cbf* p0 = src + ((size_t)n2 * KWV + kw)*CCH + c0 + c;
        const cbf* p1 = p0 + (size_t)HH * KWV * CCH;
        float2 u[16];
        #pragma unroll
        for (int n1 = 0; n1 < 16; n1++) {
            float2 a = b2f(*p0), b = b2f(*p1);
            p0 += hstep; p1 += hstep;
            u[n1] = bb ? make_float2(a.x - b.x, a.y - b.y)
                       : make_float2(a.x + b.x, a.y + b.y);
        }
        __syncthreads();
        fft16r(u);
        #pragma unroll
        for (int k1 = 0; k1 < 16; k1++)
            Ys[bb][k1][n2][c] = cmul(u[FFI(k1)], stw[k1*n2]);
    }
    __syncthreads();
    #pragma unroll
    for (int r = 0; r < 2; r++) {
        int t = tid + 256*r;
        int c = t & 15, k1 = (t >> 4) & 15, bb = t >> 8;
        float2 v[8];
        #pragma unroll
        for (int n2 = 0; n2 < 8; n2++) v[n2] = Ys[bb][k1][n2][c];
        fft8r(v);
        const size_t kstep = (size_t)16 * KWV * CCH;
        const size_t base = (((size_t)bb*HH + k1)*KWV + kw)*CCH + c0 + c;
        if (FWD) {
            __nv_bfloat16* q = (__nv_bfloat16*)g_A + base;
            #pragma unroll
            for (int k2 = 0; k2 < 8; k2++) {
                *q = __float2bfloat16(v[k2].x + v[k2].y);
                q += kstep;
            }
        } else {
            cbf* q = g_B + base;
            #pragma unroll
            for (int k2 = 0; k2 < 8; k2++) {
                *q = f2b(v[k2]);
                q += kstep;
            }
        }
    }
}

// ---------------- HMMA MLP: g_A(av) + g_C(an) -> s (bf16) in g_B ----------------
#define MO_AS 0
#define MO_AD 26624
#define MO_W0 53248
#define MO_W1 73216
#define MSM   93184
#define ASTR  104
#define SOP   133

__device__ __forceinline__ void mmaGemv(uint32_t aSb, uint32_t aDb,
    const __nv_bfloat16* __restrict__ w0, const __nv_bfloat16* __restrict__ w1v,
    int warpM, int warpN, int lane, int g, int tig,
    float U[2][3][4], float V[2][3][4])
{
    #pragma unroll
    for (int mi = 0; mi < 2; mi++)
        #pragma unroll
        for (int ni = 0; ni < 3; ni++)
            #pragma unroll
            for (int j = 0; j < 4; j++) { U[mi][ni][j] = 0.f; V[mi][ni][j] = 0.f; }
    const uint32_t lrow = (uint32_t)(lane & 15) * (ASTR*2);
    const uint32_t lcol = (uint32_t)((lane >> 4) << 4);
    #pragma unroll
    for (int kb = 0; kb < 6; kb++) {
        const int kc = kb * 16;
        unsigned aS0[4], aS1[4], aD0[4], aD1[4];
        uint32_t base = lrow + lcol + kc*2;
        ldmA(aS0, aSb + (uint32_t)(warpM*32     )*(ASTR*2) + base);
        ldmA(aS1, aSb + (uint32_t)(warpM*32 + 16)*(ASTR*2) + base);
        ldmA(aD0, aDb + (uint32_t)(warpM*32     )*(ASTR*2) + base);
        ldmA(aD1, aDb + (uint32_t)(warpM*32 + 16)*(ASTR*2) + base);
        #pragma unroll
        for (int ni = 0; ni < 3; ni++) {
            const int orow = warpN*24 + ni*8 + g;
            unsigned b0[2], b1[2];
            b0[0] = *(const unsigned*)&w0 [orow*WSTR + kc + 2*tig];
            b0[1] = *(const unsigned*)&w0 [orow*WSTR + kc + 8 + 2*tig];
            b1[0] = *(const unsigned*)&w1v[orow*WSTR + kc + 2*tig];
            b1[1] = *(const unsigned*)&w1v[orow*WSTR + kc + 8 + 2*tig];
            mma16816(U[0][ni], aS0, b0);
            mma16816(U[1][ni], aS1, b0);
            mma16816(V[0][ni], aD0, b1);
            mma16816(V[1][ni], aD1, b1);
        }
    }
}

__global__ __launch_bounds__(512, 1) void kMLP(const float* __restrict__ b1,
                                               const float* __restrict__ b2)
{
    extern __shared__ char smc[];
    __nv_bfloat16* aS  = (__nv_bfloat16*)(smc + MO_AS);
    __nv_bfloat16* aD  = (__nv_bfloat16*)(smc + MO_AD);
    __nv_bfloat16* wS0 = (__nv_bfloat16*)(smc + MO_W0);
    __nv_bfloat16* wS1 = (__nv_bfloat16*)(smc + MO_W1);
    const uint32_t aSb = smem_u32(aS), aDb = smem_u32(aD);
    const int n = blockIdx.y, p0 = blockIdx.x * 128, tid = threadIdx.x;
    const int wid = tid >> 5, lane = tid & 31;
    const int warpM = wid >> 2, warpN = wid & 3;
    const int g = lane >> 2, tig = lane & 3;

    {
        const uint4* s0 = (const uint4*)g_Wb[0][n];
        const uint4* s1 = (const uint4*)g_Wb[1][n];
        for (int e = tid; e < (BS*WSTR)/8; e += 512) {
            ((uint4*)wS0)[e] = s0[e];
            ((uint4*)wS1)[e] = s1[e];
        }
    }
    {
        const __nv_bfloat16* gAv = (const __nv_bfloat16*)g_A + (size_t)p0*CCH + n*BS;
        const __nv_bfloat16* gAn = g_C + (size_t)p0*CCH + n*BS;
        for (int e = tid; e < 6144; e += 512) {
            int p = e / 48, c = (e - 48*p) * 2;
            float2 av = b2f(*(const cbf*)&gAv[(size_t)p*CCH + c]);
            float2 an = b2f(*(const cbf*)&gAn[(size_t)p*CCH + c]);
            *(cbf*)&aS[p*ASTR + c] = f2b(make_float2(av.x + an.x, av.y + an.y));
            *(cbf*)&aD[p*ASTR + c] = f2b(make_float2(av.x - an.x, av.y - an.y));
        }
    }
    __syncthreads();

    float U[2][3][4], V[2][3][4], keep[2][3][4];

    // ===== layer 1 =====
    mmaGemv(aSb, aDb, wS0, wS1, warpM, warpN, lane, g, tig, U, V);
    __syncthreads();
    #pragma unroll
    for (int mi = 0; mi < 2; mi++)
        #pragma unroll
        for (int ni = 0; ni < 3; ni++) {
            const int o = warpN*24 + ni*8 + 2*tig;
            const float bk0 = b1[n*BS + o],        bk1 = b1[n*BS + o + 1];
            const float bn0 = b1[(NB+n)*BS + o],   bn1 = b1[(NB+n)*BS + o + 1];
            const int p = warpM*32 + mi*16 + g;
            #pragma unroll
            for (int hh = 0; hh < 2; hh++) {
                float Uu0 = U[mi][ni][2*hh], Uu1 = U[mi][ni][2*hh+1];
                float Vv0 = V[mi][ni][2*hh], Vv1 = V[mi][ni][2*hh+1];
                float k0 = fmaxf(fmaf(0.5f, Uu0 + Vv0, bk0), 0.f);
                float n0 = fmaxf(fmaf(0.5f, Uu0 - Vv0, bn0), 0.f);
                float k1 = fmaxf(fmaf(0.5f, Uu1 + Vv1, bk1), 0.f);
                float n1 = fmaxf(fmaf(0.5f, Uu1 - Vv1, bn1), 0.f);
                keep[mi][ni][2*hh] = n0; keep[mi][ni][2*hh+1] = n1;
                const int pp = p + 8*hh;
                *(__nv_bfloat162*)&aS[pp*ASTR + o] = __floats2bfloat162_rn(k0 + n0, k1 + n1);
                *(__nv_bfloat162*)&aD[pp*ASTR + o] = __floats2bfloat162_rn(k0 - n0, k1 - n1);
            }
        }
    {
        const uint4* s0 = (const uint4*)g_Wb[2][n];
        const uint4* s1 = (const uint4*)g_Wb[3][n];
        for (int e = tid; e < (BS*WSTR)/8; e += 512) {
            ((uint4*)wS0)[e] = s0[e];
            ((uint4*)wS1)[e] = s1[e];
        }
    }
    __syncthreads();

    // ===== layer 2 (o2_k) =====
    mmaGemv(aSb, aDb, wS0, wS1, warpM, warpN, lane, g, tig, U, V);
    __syncthreads();
    #pragma unroll
    for (int mi = 0; mi < 2; mi++)
        #pragma unroll
        for (int ni = 0; ni < 3; ni++) {
            const int o = warpN*24 + ni*8 + 2*tig;
            const float bk0 = b2[n*BS + o], bk1 = b2[n*BS + o + 1];
            const int p = warpM*32 + mi*16 + g;
            #pragma unroll
            for (int hh = 0; hh < 2; hh++) {
                float ok0 = fmaf(0.5f, U[mi][ni][2*hh]   + V[mi][ni][2*hh],   bk0);
                float ok1 = fmaf(0.5f, U[mi][ni][2*hh+1] + V[mi][ni][2*hh+1], bk1);
                float un0 = keep[mi][ni][2*hh], un1 = keep[mi][ni][2*hh+1];
                keep[mi][ni][2*hh] = ok0; keep[mi][ni][2*hh+1] = ok1;
                const int pp = p + 8*hh;
                *(__nv_bfloat162*)&aS[pp*ASTR + o] = __floats2bfloat162_rn(un0 + ok0, un1 + ok1);
                *(__nv_bfloat162*)&aD[pp*ASTR + o] = __floats2bfloat162_rn(un0 - ok0, un1 - ok1);  // o2_nk uses o2_k
            }
        }
    __syncthreads();

    // ===== layer 2 (o2_nk) + soft-threshold =====
    mmaGemv(aSb, aDb, wS0, wS1, warpM, warpN, lane, g, tig, U, V);
    __syncthreads();
    float* sOut = (float*)(smc + MO_AS);
    #pragma unroll
    for (int mi = 0; mi < 2; mi++)
        #pragma unroll
        for (int ni = 0; ni < 3; ni++) {
            const int o = warpN*24 + ni*8 + 2*tig;
            const float bn0 = b2[(NB+n)*BS + o], bn1 = b2[(NB+n)*BS + o + 1];
            const int p = warpM*32 + mi*16 + g;
            #pragma unroll
            for (int hh = 0; hh < 2; hh++) {
                float o2n0 = fmaf(0.5f, U[mi][ni][2*hh]   + V[mi][ni][2*hh],   bn0);
                float o2n1 = fmaf(0.5f, U[mi][ni][2*hh+1] + V[mi][ni][2*hh+1], bn1);
                float t0 = keep[mi][ni][2*hh]   + o2n0;
                float t1 = keep[mi][ni][2*hh+1] + o2n1;
                const int pp = p + 8*hh;
                sOut[o*SOP + pp]     = copysignf(fmaxf(fabsf(t0) - 0.01f, 0.f), t0);
                sOut[(o+1)*SOP + pp] = copysignf(fmaxf(fabsf(t1) - 0.01f, 0.f), t1);
            }
        }
    __syncthreads();
    __nv_bfloat16* outp = (__nv_bfloat16*)g_B;
    for (int e = tid; e < 12288; e += 512) {
        int p = e / 96, c = e - 96*p;
        outp[(size_t)(p0 + p)*CCH + n*BS + c] = __float2bfloat16(sOut[c*SOP + p]);
    }
}

// ---------------- inverse W-FFT (65 -> 256) + scale + residual : g_B -> out ----------------
__global__ __launch_bounds__(256) void kIW(const float* __restrict__ x, float* __restrict__ out)
{
    __shared__ float2 Zs[KWV*16];
    __shared__ float2 Ys[256*17];
    __shared__ float2 stw[256];
    const int bh = blockIdx.x, c0 = blockIdx.y * 16, tid = threadIdx.x;
    if (tid < 256) stw[tid] = g_tw256[tid];
    const cbf* __restrict__ zp = g_B + (size_t)bh*KWV*CCH + c0;
    for (int e = tid; e < KWV*16; e += 256) {
        int w = e >> 4, c = e & 15;
        Zs[e] = b2f(zp[(size_t)w*CCH + c]);
    }
    __syncthreads();
    for (int e = tid; e < 4096; e += 256) {
        int c = e & 15, n2 = (e >> 4) & 15, k1 = e >> 8;
        float2 acc = make_float2(0.f, 0.f);
        int idx = (k1 * n2) & 255, step = (k1 * 16) & 255;
        int nmax = (n2 == 0) ? 5 : 4;
        for (int n1 = 0; n1 < nmax; n1++) {
            int w = (n1 << 4) + n2;
            cmadd(acc, Zs[w*16 + c], stw[idx]);
            idx = (idx + step) & 255;
        }
        Ys[(k1*16 + n2)*17 + c] = acc;
    }
    __syncthreads();
    const float invN = 1.0f / 50331648.0f;
    {
        const int k1 = tid >> 4, c = tid & 15;
        float2 v[16];
        #pragma unroll
        for (int n2 = 0; n2 < 16; n2++) v[n2] = Ys[(k1*16 + n2)*17 + c];
        fft16r(v);
        #pragma unroll
        for (int k2 = 0; k2 < 16; k2++) {
            float2 acc = v[FFI(k2)];
            size_t a = ((size_t)bh*WW + k1 + 16*k2)*CCH + c0 + c;
            out[a] = fmaf(acc.x + acc.y, invN, x[a]);
        }
    }
}

extern "C" void kernel_launch(void* const* d_in, const int* in_sizes, int n_in,
                              void* d_out, int out_size)
{
    const float* x  = (const float*)d_in[0];
    const float* w1 = (const float*)d_in[1];
    const float* b1 = (const float*)d_in[2];
    const float* w2 = (const float*)d_in[3];
    const float* b2 = (const float*)d_in[4];
    float* out = (float*)d_out;

    cudaFuncSetAttribute(kMLP,   cudaFuncAttributeMaxDynamicSharedMemorySize, MSM);
    cudaFuncSetAttribute(kF1,    cudaFuncAttributeMaxDynamicSharedMemorySize, 54272);
    cudaFuncSetAttribute(kFC<0>, cudaFuncAttributeMaxDynamicSharedMemorySize, 30720);
    cudaFuncSetAttribute(kFC<1>, cudaFuncAttributeMaxDynamicSharedMemorySize, 30720);

    kPrep<<<290, 1024>>>(w1, w2);
    kF1 <<<dim3(BB*HH, CCH/16), 256, 54272>>>(x);   // x -> A (cplx) + C (an)
    kFC<0><<<NPOS/4, 192, 30720>>>();               // A -> B
    kFHB<1><<<dim3(KWV, CCH/16), 256>>>();          // B -> av (real bf16) in A
    kMLP<<<dim3(NPOS/128, NB), 512, MSM>>>(b1, b2); // A(av)+C(an) -> s(bf16) in B
    kFC<1><<<NPOS/4, 192, 30720>>>();               // B(real bf16) -> A
    kFHB<0><<<dim3(KWV, CCH/16), 256>>>();          // A -> B
    kIW <<<dim3(BB*HH, CCH/16), 256>>>(x, out);     // B -> out
}

// round 17
// speedup vs baseline: 1.2466x; 1.0119x over previous
#include <cuda_runtime.h>
#include <cuda_bf16.h>
#include <math.h>
#include <stdint.h>

#define BB 2
#define HH 128
#define WW 256
#define CCH 768
#define KWV 65
#define NB 8
#define BS 96
#define NPOS (BB*HH*KWV)
#define SLABN (NPOS*CCH)

typedef unsigned long long u64;
typedef __nv_bfloat162 cbf;

__device__ cbf g_A[SLABN];                 // 51 MB: complex slab / av real slab (bf16)
__device__ cbf g_B[SLABN];                 // 51 MB
__device__ __nv_bfloat16 g_C[SLABN];       // 25.5 MB: an gather slab (real bf16)
__device__ float2 g_tw256[256];
__device__ float2 g_tw768[768];
__device__ float2 g_tw128[128];

#define WSTR 104
__device__ __nv_bfloat16 g_Wb[4][NB][BS*WSTR];   // pre-transposed bf16 weights [o][i]

__device__ __forceinline__ float2 b2f(cbf v) {
    return make_float2(__bfloat162float(v.x), __bfloat162float(v.y));
}
__device__ __forceinline__ cbf f2b(float2 v) {
    return __floats2bfloat162_rn(v.x, v.y);
}
__device__ __forceinline__ void cmadd(float2& acc, float2 z, float2 t) {
    acc.x = fmaf(z.x, t.x, fmaf(-z.y, t.y, acc.x));
    acc.y = fmaf(z.x, t.y, fmaf( z.y, t.x, acc.y));
}
__device__ __forceinline__ float2 cmul(float2 a, float2 b) {
    return make_float2(a.x*b.x - a.y*b.y, a.x*b.y + a.y*b.x);
}

// ---------------- register FFT primitives ----------------
#define FC1 0.92387953251128674f
#define FS1 0.38268343236508977f
#define FR  0.70710678118654752f

__device__ __forceinline__ float2 cadd2(float2 a, float2 b) {
    return make_float2(fmaf(b.x, 1.0f, a.x), fmaf(b.y, 1.0f, a.y));
}
__device__ __forceinline__ float2 csub2(float2 a, float2 b) {
    return make_float2(fmaf(b.x, -1.0f, a.x), fmaf(b.y, -1.0f, a.y));
}
__device__ __forceinline__ float2 cmulK(float2 z, float C, float S) {
    return make_float2(fmaf(z.x, C, -z.y*S), fmaf(z.y, C, z.x*S));
}
__device__ __forceinline__ void dft4(float2& a, float2& b, float2& c, float2& d) {
    float2 apc = cadd2(a, c), amc = csub2(a, c);
    float2 bpd = cadd2(b, d), bmd = csub2(b, d);
    float2 jb = make_float2(bmd.y, -bmd.x);
    a = cadd2(apc, bpd);
    b = cadd2(amc, jb);
    c = csub2(apc, bpd);
    d = csub2(amc, jb);
}
#define FFI(k) (4*((k)&3) + ((k)>>2))
__device__ __forceinline__ void fft16r(float2 v[16]) {
    dft4(v[0], v[4], v[8],  v[12]);
    dft4(v[1], v[5], v[9],  v[13]);
    dft4(v[2], v[6], v[10], v[14]);
    dft4(v[3], v[7], v[11], v[15]);
    v[5]  = cmulK(v[5],  FC1, -FS1);
    v[6]  = cmulK(v[6],  FR,  -FR );
    v[7]  = cmulK(v[7],  FS1, -FC1);
    v[9]  = cmulK(v[9],  FR,  -FR );
    v[10] = make_float2(v[10].y, -v[10].x);
    v[11] = cmulK(v[11], -FR,  -FR );
    v[13] = cmulK(v[13], FS1, -FC1);
    v[14] = cmulK(v[14], -FR,  -FR );
    v[15] = cmulK(v[15], -FC1,  FS1);
    dft4(v[0],  v[1],  v[2],  v[3]);
    dft4(v[4],  v[5],  v[6],  v[7]);
    dft4(v[8],  v[9],  v[10], v[11]);
    dft4(v[12], v[13], v[14], v[15]);
}
__device__ __forceinline__ void fft8r(float2 v[8]) {
    float2 a0 = cadd2(v[0], v[4]), a1 = cadd2(v[1], v[5]);
    float2 a2 = cadd2(v[2], v[6]), a3 = cadd2(v[3], v[7]);
    float2 b0 = csub2(v[0], v[4]);
    float2 t1 = csub2(v[1], v[5]);
    float2 t2 = csub2(v[2], v[6]);
    float2 t3 = csub2(v[3], v[7]);
    float2 b1 = cmulK(t1, FR, -FR);
    float2 b2 = make_float2(t2.y, -t2.x);
    float2 b3 = cmulK(t3, -FR, -FR);
    dft4(a0, a1, a2, a3);
    dft4(b0, b1, b2, b3);
    v[0] = a0; v[2] = a1; v[4] = a2; v[6] = a3;
    v[1] = b0; v[3] = b1; v[5] = b2; v[7] = b3;
}

// ---------------- HMMA helpers ----------------
__device__ __forceinline__ uint32_t smem_u32(const void* p) {
    uint32_t a;
    asm("{ .reg .u64 t; cvta.to.shared.u64 t, %1; cvt.u32.u64 %0, t; }" : "=r"(a) : "l"(p));
    return a;
}
__device__ __forceinline__ void ldmA(unsigned r[4], uint32_t addr) {
    asm volatile("ldmatrix.sync.aligned.m8n8.x4.shared.b16 {%0,%1,%2,%3}, [%4];"
        : "=r"(r[0]),"=r"(r[1]),"=r"(r[2]),"=r"(r[3]) : "r"(addr));
}
__device__ __forceinline__ void mma16816(float d[4], const unsigned a[4], const unsigned b[2]) {
    asm volatile("mma.sync.aligned.m16n8k16.row.col.f32.bf16.bf16.f32 "
        "{%0,%1,%2,%3}, {%4,%5,%6,%7}, {%8,%9}, {%0,%1,%2,%3};"
        : "+f"(d[0]),"+f"(d[1]),"+f"(d[2]),"+f"(d[3])
        : "r"(a[0]),"r"(a[1]),"r"(a[2]),"r"(a[3]), "r"(b[0]),"r"(b[1]));
}

// ---------------- prep: twiddles + bf16 weight transposition ----------------
__global__ void kPrep(const float* __restrict__ w1, const float* __restrict__ w2)
{
    int t = blockIdx.x * blockDim.x + threadIdx.x;
    const double TP = 6.283185307179586476925286766559;
    if (t < 768) {
        double s, c;
        sincos(-TP * (double)t / 768.0, &s, &c);
        g_tw768[t] = make_float2((float)c, (float)s);
        if (t < 256) { sincos(-TP*(double)t/256.0, &s, &c); g_tw256[t] = make_float2((float)c,(float)s); }
        if (t < 128) { sincos(-TP*(double)t/128.0, &s, &c); g_tw128[t] = make_float2((float)c,(float)s); }
    }
    int stride = gridDim.x * blockDim.x;
    for (int e = t; e < 4*NB*BS*BS; e += stride) {
        int m = e / (NB*BS*BS);
        int r = e - m*(NB*BS*BS);
        int n = r / (BS*BS);
        int q = r - n*(BS*BS);
        int i = q / BS, o = q - i*BS;
        const float* src = (m < 2) ? (w1 + (size_t)(m*NB + n)*9216)
                                   : (w2 + (size_t)((m-2)*NB + n)*9216);
        g_Wb[m][n][o*WSTR + i] = __float2bfloat16(src[i*96 + o]);
    }
}

// ---------------- forward W-FFT (256=16x16) pruned kw<65 + an emit : x -> g_A, g_C ----------------
__global__ __launch_bounds__(256) void kF1(const float* __restrict__ x)
{
    extern __shared__ float smF1[];
    float*  Xs  = smF1;
    float2* Ys  = (float2*)(smF1 + 4352);
    float2* stw = Ys + 4352;
    const int bh = blockIdx.x, c0 = blockIdx.y * 16, tid = threadIdx.x;
    if (tid < 256) stw[tid] = g_tw256[tid];
    const float* xp = x + (size_t)bh * (WW*CCH) + c0;
    for (int e = tid; e < 1024; e += 256) {
        int w = e >> 2, c4 = (e & 3) * 4;
        float4 v = *(const float4*)(xp + (size_t)w * CCH + c4);
        Xs[w*17 + c4]     = v.x;
        Xs[w*17 + c4 + 1] = v.y;
        Xs[w*17 + c4 + 2] = v.z;
        Xs[w*17 + c4 + 3] = v.w;
    }
    __syncthreads();
    {
        const int b = bh >> 7, h = bh & 127;
        const int hn = (HH - h) & (HH - 1);
        __nv_bfloat16* cp = g_C + (((size_t)b*HH + hn)*KWV)*CCH + c0;
        for (int e = tid; e < KWV*8; e += 256) {
            int kw = e >> 3, c = (e & 7) * 2;
            int wn = (WW - kw) & (WW - 1);
            *(cbf*)&cp[(size_t)kw*CCH + c] =
                __floats2bfloat162_rn(Xs[wn*17 + c], Xs[wn*17 + c + 1]);
        }
    }
    {
        const int n2 = tid >> 4, c = tid & 15;
        float2 u[16];
        #pragma unroll
        for (int n1 = 0; n1 < 16; n1++) u[n1] = make_float2(Xs[(16*n1 + n2)*17 + c], 0.f);
        fft16r(u);
        #pragma unroll
        for (int k1 = 0; k1 < 16; k1++)
            Ys[(k1*16 + n2)*17 + c] = cmul(u[FFI(k1)], stw[n2*k1]);
    }
    __syncthreads();
    {
        const int k1 = tid >> 4, c = tid & 15;
        float2 v[16];
        #pragma unroll
        for (int n2 = 0; n2 < 16; n2++) v[n2] = Ys[(k1*16 + n2)*17 + c];
        fft16r(v);
        cbf* dst = g_A + ((size_t)bh*KWV)*CCH + c0 + c;
        #pragma unroll
        for (int k2 = 0; k2 < 4; k2++)
            dst[(size_t)(k1 + 16*k2)*CCH] = f2b(v[FFI(k2)]);
        if (k1 == 0)
            dst[(size_t)64*CCH] = f2b(v[FFI(4)]);
    }
}

// ---------------- C-FFT 768 = 16x16x3 (bf16 intermediates, 30.7KB smem) ----------------
template<int RIN>
__global__ __launch_bounds__(192) void kFC()
{
    extern __shared__ char smCb[];
    cbf* zb      = (cbf*)smCb;
    cbf* Ab      = (cbf*)(smCb + 12288);
    float2* stw256 = (float2*)(smCb + 24576);
    float2* stw768 = (float2*)(smCb + 26624);
    const int tid = threadIdx.x;
    const int r = tid / 48, l = tid - r*48;
    const size_t row0 = (size_t)blockIdx.x * 4;
    for (int e = tid; e < 256; e += 192) stw256[e] = g_tw256[e];
    for (int e = tid; e < 512; e += 192) stw768[e] = g_tw768[e];
    if (RIN) {
        const __nv_bfloat16* sp = (const __nv_bfloat16*)g_B;
        for (int e = tid; e < 3072; e += 192) {
            cbf z; z.x = sp[row0*768 + e]; z.y = __float2bfloat16(0.f);
            zb[e] = z;
        }
    } else {
        const uint4* sp = (const uint4*)(g_A + row0*768);
        uint4* dp = (uint4*)zb;
        for (int e = tid; e < 768; e += 192)
            dp[e] = sp[e];
    }
    __syncthreads();
    {
        const int n3 = l >> 4, n2 = l & 15;
        float2 u[16];
        #pragma unroll
        for (int n1 = 0; n1 < 16; n1++) u[n1] = b2f(zb[r*768 + n3 + 3*n2 + 48*n1]);
        fft16r(u);
        #pragma unroll
        for (int k1 = 0; k1 < 16; k1++)
            Ab[r*768 + (n3*16 + k1)*16 + n2] = f2b(cmul(u[FFI(k1)], stw256[n2*k1]));
    }
    __syncthreads();
    {
        const int n3 = l >> 4, k1 = l & 15;
        float2 v[16];
        #pragma unroll
        for (int n2 = 0; n2 < 16; n2++) v[n2] = b2f(Ab[r*768 + (n3*16 + k1)*16 + n2]);
        fft16r(v);
        #pragma unroll
        for (int k2 = 0; k2 < 16; k2++)
            zb[r*768 + (n3*16 + k1)*16 + k2] = f2b(v[FFI(k2)]);
    }
    __syncthreads();
    {
        cbf* dst = RIN ? g_A : g_B;
        const float s3 = 0.86602540378443865f;
        for (int e = tid; e < 1024; e += 192) {
            const int rr = e >> 8, m = e & 255;
            const int k1 = m & 15, k2 = m >> 4;
            float2 b0 = b2f(zb[rr*768 +       k1*16 + k2]);
            float2 b1 = cmul(b2f(zb[rr*768 + 256 + k1*16 + k2]), stw768[m]);
            float2 b2 = cmul(b2f(zb[rr*768 + 512 + k1*16 + k2]), stw768[2*m]);
            float2 t1 = make_float2(b1.x + b2.x, b1.y + b2.y);
            float2 t2 = make_float2(b1.x - b2.x, b1.y - b2.y);
            dst[(row0+rr)*768 + m] = f2b(make_float2(b0.x + t1.x, b0.y + t1.y));
            float xr = fmaf(-0.5f, t1.x, b0.x);
            float xi = fmaf(-0.5f, t1.y, b0.y);
            dst[(row0+rr)*768 + m + 256] = f2b(make_float2(fmaf( s3, t2.y, xr), fmaf(-s3, t2.x, xi)));
            dst[(row0+rr)*768 + m + 512] = f2b(make_float2(fmaf(-s3, t2.y, xr), fmaf( s3, t2.x, xi)));
        }
    }
}

// ---------------- H-FFT (128=16x8) + B-FFT.  FWD=1: g_B -> av (real bf16) in g_A ; FWD=0: g_A -> g_B ----------------
template<int FWD>
__global__ __launch_bounds__(256) void kFHB()
{
    __shared__ float2 Ys[2][16][8][16];
    __shared__ float2 stw[128];
    const cbf* __restrict__ src = FWD ? g_B : g_A;
    const int kw = blockIdx.x, c0 = blockIdx.y * 16, tid = threadIdx.x;
    if (tid < 128) stw[tid] = g_tw128[tid];
    {
        const int c = tid & 15, n2 = (tid >> 4) & 7, bb = tid >> 7;
        const size_t hstep = (size_t)8 * KWV * CCH;
        const cbf* p0 = src + ((size_t)n2 * KWV + kw)*CCH + c0 + c;
        const cbf* p1 = p0 + (size_t)HH * KWV * CCH;
        float2 u[16];
        #pragma unroll
        for (int n1 = 0; n1 < 16; n1++) {
            float2 a = b2f(*p0), b = b2f(*p1);
            p0 += hstep; p1 += hstep;
            u[n1] = bb ? make_float2(a.x - b.x, a.y - b.y)
                       : make_float2(a.x + b.x, a.y + b.y);
        }
        __syncthreads();
        fft16r(u);
        #pragma unroll
        for (int k1 = 0; k1 < 16; k1++)
            Ys[bb][k1][n2][c] = cmul(u[FFI(k1)], stw[k1*n2]);
    }
    __syncthreads();
    #pragma unroll
    for (int r = 0; r < 2; r++) {
        int t = tid + 256*r;
        int c = t & 15, k1 = (t >> 4) & 15, bb = t >> 8;
        float2 v[8];
        #pragma unroll
        for (int n2 = 0; n2 < 8; n2++) v[n2] = Ys[bb][k1][n2][c];
        fft8r(v);
        const size_t kstep = (size_t)16 * KWV * CCH;
        const size_t base = (((size_t)bb*HH + k1)*KWV + kw)*CCH + c0 + c;
        if (FWD) {
            __nv_bfloat16* q = (__nv_bfloat16*)g_A + base;
            #pragma unroll
            for (int k2 = 0; k2 < 8; k2++) {
                *q = __float2bfloat16(v[k2].x + v[k2].y);
                q += kstep;
            }
        } else {
            cbf* q = g_B + base;
            #pragma unroll
            for (int k2 = 0; k2 < 8; k2++) {
                *q = f2b(v[k2]);
                q += kstep;
            }
        }
    }
}

// ---------------- HMMA MLP (64 pos/block, 256 thr, 2 CTAs/SM): g_A(av)+g_C(an) -> s(bf16) in g_B ----------------
#define MP    64
#define MO_AS 0
#define MO_AD 13312
#define MO_W0 26624
#define MO_W1 46592
#define MSM   66560
#define ASTR  104
#define SOP   67

__device__ __forceinline__ void mmaGemv(uint32_t aSb, uint32_t aDb,
    const __nv_bfloat16* __restrict__ w0, const __nv_bfloat16* __restrict__ w1v,
    int warpM, int warpN, int lane, int g, int tig,
    float U[2][3][4], float V[2][3][4])
{
    #pragma unroll
    for (int mi = 0; mi < 2; mi++)
        #pragma unroll
        for (int ni = 0; ni < 3; ni++)
            #pragma unroll
            for (int j = 0; j < 4; j++) { U[mi][ni][j] = 0.f; V[mi][ni][j] = 0.f; }
    const uint32_t lrow = (uint32_t)(lane & 15) * (ASTR*2);
    const uint32_t lcol = (uint32_t)((lane >> 4) << 4);
    #pragma unroll
    for (int kb = 0; kb < 6; kb++) {
        const int kc = kb * 16;
        unsigned aS0[4], aS1[4], aD0[4], aD1[4];
        uint32_t base = lrow + lcol + kc*2;
        ldmA(aS0, aSb + (uint32_t)(warpM*32     )*(ASTR*2) + base);
        ldmA(aS1, aSb + (uint32_t)(warpM*32 + 16)*(ASTR*2) + base);
        ldmA(aD0, aDb + (uint32_t)(warpM*32     )*(ASTR*2) + base);
        ldmA(aD1, aDb + (uint32_t)(warpM*32 + 16)*(ASTR*2) + base);
        #pragma unroll
        for (int ni = 0; ni < 3; ni++) {
            const int orow = warpN*24 + ni*8 + g;
            unsigned b0[2], b1[2];
            b0[0] = *(const unsigned*)&w0 [orow*WSTR + kc + 2*tig];
            b0[1] = *(const unsigned*)&w0 [orow*WSTR + kc + 8 + 2*tig];
            b1[0] = *(const unsigned*)&w1v[orow*WSTR + kc + 2*tig];
            b1[1] = *(const unsigned*)&w1v[orow*WSTR + kc + 8 + 2*tig];
            mma16816(U[0][ni], aS0, b0);
            mma16816(U[1][ni], aS1, b0);
            mma16816(V[0][ni], aD0, b1);
            mma16816(V[1][ni], aD1, b1);
        }
    }
}

__global__ __launch_bounds__(256, 2) void kMLP(const float* __restrict__ b1,
                                               const float* __restrict__ b2)
{
    extern __shared__ char smc[];
    __nv_bfloat16* aS  = (__nv_bfloat16*)(smc + MO_AS);
    __nv_bfloat16* aD  = (__nv_bfloat16*)(smc + MO_AD);
    __nv_bfloat16* wS0 = (__nv_bfloat16*)(smc + MO_W0);
    __nv_bfloat16* wS1 = (__nv_bfloat16*)(smc + MO_W1);
    const uint32_t aSb = smem_u32(aS), aDb = smem_u32(aD);
    const int n = blockIdx.y, p0 = blockIdx.x * MP, tid = threadIdx.x;
    const int wid = tid >> 5, lane = tid & 31;
    const int warpM = wid >> 2, warpN = wid & 3;
    const int g = lane >> 2, tig = lane & 3;

    {
        const uint4* s0 = (const uint4*)g_Wb[0][n];
        const uint4* s1 = (const uint4*)g_Wb[1][n];
        for (int e = tid; e < (BS*WSTR)/8; e += 256) {
            ((uint4*)wS0)[e] = s0[e];
            ((uint4*)wS1)[e] = s1[e];
        }
    }
    {
        const __nv_bfloat16* gAv = (const __nv_bfloat16*)g_A + (size_t)p0*CCH + n*BS;
        const __nv_bfloat16* gAn = g_C + (size_t)p0*CCH + n*BS;
        for (int e = tid; e < MP*48; e += 256) {
            int p = e / 48, c = (e - 48*p) * 2;
            float2 av = b2f(*(const cbf*)&gAv[(size_t)p*CCH + c]);
            float2 an = b2f(*(const cbf*)&gAn[(size_t)p*CCH + c]);
            *(cbf*)&aS[p*ASTR + c] = f2b(make_float2(av.x + an.x, av.y + an.y));
            *(cbf*)&aD[p*ASTR + c] = f2b(make_float2(av.x - an.x, av.y - an.y));
        }
    }
    __syncthreads();

    float U[2][3][4], V[2][3][4], keep[2][3][4];

    // ===== layer 1 =====
    mmaGemv(aSb, aDb, wS0, wS1, warpM, warpN, lane, g, tig, U, V);
    __syncthreads();
    #pragma unroll
    for (int mi = 0; mi < 2; mi++)
        #pragma unroll
        for (int ni = 0; ni < 3; ni++) {
            const int o = warpN*24 + ni*8 + 2*tig;
            const float bk0 = b1[n*BS + o],        bk1 = b1[n*BS + o + 1];
            const float bn0 = b1[(NB+n)*BS + o],   bn1 = b1[(NB+n)*BS + o + 1];
            const int p = warpM*32 + mi*16 + g;
            #pragma unroll
            for (int hh = 0; hh < 2; hh++) {
                float Uu0 = U[mi][ni][2*hh], Uu1 = U[mi][ni][2*hh+1];
                float Vv0 = V[mi][ni][2*hh], Vv1 = V[mi][ni][2*hh+1];
                float k0 = fmaxf(fmaf(0.5f, Uu0 + Vv0, bk0), 0.f);
                float n0 = fmaxf(fmaf(0.5f, Uu0 - Vv0, bn0), 0.f);
                float k1 = fmaxf(fmaf(0.5f, Uu1 + Vv1, bk1), 0.f);
                float n1 = fmaxf(fmaf(0.5f, Uu1 - Vv1, bn1), 0.f);
                keep[mi][ni][2*hh] = n0; keep[mi][ni][2*hh+1] = n1;
                const int pp = p + 8*hh;
                *(__nv_bfloat162*)&aS[pp*ASTR + o] = __floats2bfloat162_rn(k0 + n0, k1 + n1);
                *(__nv_bfloat162*)&aD[pp*ASTR + o] = __floats2bfloat162_rn(k0 - n0, k1 - n1);
            }
        }
    {
        const uint4* s0 = (const uint4*)g_Wb[2][n];
        const uint4* s1 = (const uint4*)g_Wb[3][n];
        for (int e = tid; e < (BS*WSTR)/8; e += 256) {
            ((uint4*)wS0)[e] = s0[e];
            ((uint4*)wS1)[e] = s1[e];
        }
    }
    __syncthreads();

    // ===== layer 2 (o2_k) =====
    mmaGemv(aSb, aDb, wS0, wS1, warpM, warpN, lane, g, tig, U, V);
    __syncthreads();
    #pragma unroll
    for (int mi = 0; mi < 2; mi++)
        #pragma unroll
        for (int ni = 0; ni < 3; ni++) {
            const int o = warpN*24 + ni*8 + 2*tig;
            const float bk0 = b2[n*BS + o], bk1 = b2[n*BS + o + 1];
            const int p = warpM*32 + mi*16 + g;
            #pragma unroll
            for (int hh = 0; hh < 2; hh++) {
                float ok0 = fmaf(0.5f, U[mi][ni][2*hh]   + V[mi][ni][2*hh],   bk0);
                float ok1 = fmaf(0.5f, U[mi][ni][2*hh+1] + V[mi][ni][2*hh+1], bk1);
                float un0 = keep[mi][ni][2*hh], un1 = keep[mi][ni][2*hh+1];
                keep[mi][ni][2*hh] = ok0; keep[mi][ni][2*hh+1] = ok1;
                const int pp = p + 8*hh;
                *(__nv_bfloat162*)&aS[pp*ASTR + o] = __floats2bfloat162_rn(un0 + ok0, un1 + ok1);
                *(__nv_bfloat162*)&aD[pp*ASTR + o] = __floats2bfloat162_rn(un0 - ok0, un1 - ok1);  // o2_nk uses o2_k
            }
        }
    __syncthreads();

    // ===== layer 2 (o2_nk) + soft-threshold =====
    mmaGemv(aSb, aDb, wS0, wS1, warpM, warpN, lane, g, tig, U, V);
    __syncthreads();
    float* sOut = (float*)(smc + MO_AS);   // 96*SOP*4 = 25728 <= 26624 (aS+aD)
    #pragma unroll
    for (int mi = 0; mi < 2; mi++)
        #pragma unroll
        for (int ni = 0; ni < 3; ni++) {
            const int o = warpN*24 + ni*8 + 2*tig;
            const float bn0 = b2[(NB+n)*BS + o], bn1 = b2[(NB+n)*BS + o + 1];
            const int p = warpM*32 + mi*16 + g;
            #pragma unroll
            for (int hh = 0; hh < 2; hh++) {
                float o2n0 = fmaf(0.5f, U[mi][ni][2*hh]   + V[mi][ni][2*hh],   bn0);
                float o2n1 = fmaf(0.5f, U[mi][ni][2*hh+1] + V[mi][ni][2*hh+1], bn1);
                float t0 = keep[mi][ni][2*hh]   + o2n0;
                float t1 = keep[mi][ni][2*hh+1] + o2n1;
                const int pp = p + 8*hh;
                sOut[o*SOP + pp]     = copysignf(fmaxf(fabsf(t0) - 0.01f, 0.f), t0);
                sOut[(o+1)*SOP + pp] = copysignf(fmaxf(fabsf(t1) - 0.01f, 0.f), t1);
            }
        }
    __syncthreads();
    __nv_bfloat16* outp = (__nv_bfloat16*)g_B;
    for (int e = tid; e < MP*96; e += 256) {
        int p = e / 96, c = e - 96*p;
        outp[(size_t)(p0 + p)*CCH + n*BS + c] = __float2bfloat16(sOut[c*SOP + p]);
    }
}

// ---------------- inverse W-FFT (65 -> 256) + scale + residual : g_B -> out ----------------
__global__ __launch_bounds__(256) void kIW(const float* __restrict__ x, float* __restrict__ out)
{
    __shared__ float2 Zs[KWV*16];
    __shared__ float2 Ys[256*17];
    __shared__ float2 stw[256];
    const int bh = blockIdx.x, c0 = blockIdx.y * 16, tid = threadIdx.x;
    if (tid < 256) stw[tid] = g_tw256[tid];
    const cbf* __restrict__ zp = g_B + (size_t)bh*KWV*CCH + c0;
    for (int e = tid; e < KWV*16; e += 256) {
        int w = e >> 4, c = e & 15;
        Zs[e] = b2f(zp[(size_t)w*CCH + c]);
    }
    __syncthreads();
    for (int e = tid; e < 4096; e += 256) {
        int c = e & 15, n2 = (e >> 4) & 15, k1 = e >> 8;
        float2 acc = make_float2(0.f, 0.f);
        int idx = (k1 * n2) & 255, step = (k1 * 16) & 255;
        int nmax = (n2 == 0) ? 5 : 4;
        for (int n1 = 0; n1 < nmax; n1++) {
            int w = (n1 << 4) + n2;
            cmadd(acc, Zs[w*16 + c], stw[idx]);
            idx = (idx + step) & 255;
        }
        Ys[(k1*16 + n2)*17 + c] = acc;
    }
    __syncthreads();
    const float invN = 1.0f / 50331648.0f;
    {
        const int k1 = tid >> 4, c = tid & 15;
        float2 v[16];
        #pragma unroll
        for (int n2 = 0; n2 < 16; n2++) v[n2] = Ys[(k1*16 + n2)*17 + c];
        fft16r(v);
        #pragma unroll
        for (int k2 = 0; k2 < 16; k2++) {
            float2 acc = v[FFI(k2)];
            size_t a = ((size_t)bh*WW + k1 + 16*k2)*CCH + c0 + c;
            out[a] = fmaf(acc.x + acc.y, invN, x[a]);
        }
    }
}

extern "C" void kernel_launch(void* const* d_in, const int* in_sizes, int n_in,
                              void* d_out, int out_size)
{
    const float* x  = (const float*)d_in[0];
    const float* w1 = (const float*)d_in[1];
    const float* b1 = (const float*)d_in[2];
    const float* w2 = (const float*)d_in[3];
    const float* b2 = (const float*)d_in[4];
    float* out = (float*)d_out;

    cudaFuncSetAttribute(kMLP,   cudaFuncAttributeMaxDynamicSharedMemorySize, MSM);
    cudaFuncSetAttribute(kF1,    cudaFuncAttributeMaxDynamicSharedMemorySize, 54272);
    cudaFuncSetAttribute(kFC<0>, cudaFuncAttributeMaxDynamicSharedMemorySize, 30720);
    cudaFuncSetAttribute(kFC<1>, cudaFuncAttributeMaxDynamicSharedMemorySize, 30720);

    kPrep<<<290, 1024>>>(w1, w2);
    kF1 <<<dim3(BB*HH, CCH/16), 256, 54272>>>(x);   // x -> A (cplx) + C (an)
    kFC<0><<<NPOS/4, 192, 30720>>>();               // A -> B
    kFHB<1><<<dim3(KWV, CCH/16), 256>>>();          // B -> av (real bf16) in A
    kMLP<<<dim3(NPOS/MP, NB), 256, MSM>>>(b1, b2);  // A(av)+C(an) -> s(bf16) in B
    kFC<1><<<NPOS/4, 192, 30720>>>();               // B(real bf16) -> A
    kFHB<0><<<dim3(KWV, CCH/16), 256>>>();          // A -> B
    kIW <<<dim3(BB*HH, CCH/16), 256>>>(x, out);     // B -> out
}